// round 7
// baseline (speedup 1.0000x reference)
#include <cuda_runtime.h>
#include <cuda_bf16.h>
#include <cstdint>

#define BB 2
#define SS 1024
#define DMOD 1024
#define HH 16
#define DH 64
#define NR 21     // 2*MAX_REL+1
#define K3 3072   // 3 * DMOD (split-concatenated K)

// ============================================================================
// scratch (static device globals: no allocations allowed)
// ============================================================================
// pre-split projection outputs (hi/lo bf16 planes, row-major [B*S, DMOD])
__device__ __nv_bfloat16 g_Qh[BB * SS * DMOD];
__device__ __nv_bfloat16 g_Ql[BB * SS * DMOD];
__device__ __nv_bfloat16 g_Kh[BB * SS * DMOD];
__device__ __nv_bfloat16 g_Kl[BB * SS * DMOD];
__device__ __nv_bfloat16 g_Vh[BB * SS * DMOD];
__device__ __nv_bfloat16 g_Vl[BB * SS * DMOD];

// K prefix sums: P[bh][row][d] (inclusive over rows)
__device__ float g_P[BB * HH * SS * DH];

// split-concatenated bf16 operands, row-major [rows, K3]
__device__ __nv_bfloat16 g_q2[BB * SS * K3];
__device__ __nv_bfloat16 g_k2[BB * SS * K3];
__device__ __nv_bfloat16 g_v2[BB * SS * K3];
__device__ __nv_bfloat16 g_x2[BB * SS * K3];
__device__ __nv_bfloat16 g_wq2[DMOD * K3];
__device__ __nv_bfloat16 g_wk2[DMOD * K3];
__device__ __nv_bfloat16 g_wv2[DMOD * K3];
__device__ __nv_bfloat16 g_w02[DMOD * K3];

// ============================================================================
// batched split kernel: fp32 -> bf16 hi/lo, written K-concatenated.
// ============================================================================
struct SplitPack {
    const float* in[4];
    __nv_bfloat16* out[4];
};

__global__ __launch_bounds__(256) void split_multi(SplitPack p, int n, int is_act) {
    int i = blockIdx.x * blockDim.x + threadIdx.x;
    if (i >= n) return;
    const float* in = p.in[blockIdx.y];
    __nv_bfloat16* out = p.out[blockIdx.y];
    int m = i >> 10;          // K = 1024
    int k = i & 1023;
    float x = in[i];
    __nv_bfloat16 h = __float2bfloat16_rn(x);
    float r = x - __bfloat162float(h);
    __nv_bfloat16 l = __float2bfloat16_rn(r);
    size_t base = (size_t)m * K3 + k;
    out[base] = h;
    if (is_act) {
        out[base + 1024] = l;
        out[base + 2048] = h;
    } else {
        out[base + 1024] = h;
        out[base + 2048] = l;
    }
}

// ============================================================================
// mma.sync helpers
// ============================================================================
__device__ __forceinline__ uint32_t smem_u32(const void* p) {
    uint32_t a;
    asm("{ .reg .u64 t; cvta.to.shared.u64 t, %1; cvt.u32.u64 %0, t; }"
        : "=r"(a) : "l"(p));
    return a;
}

__device__ __forceinline__ void ldmx4(uint32_t& r0, uint32_t& r1,
                                      uint32_t& r2, uint32_t& r3,
                                      uint32_t addr) {
    asm volatile(
        "ldmatrix.sync.aligned.m8n8.x4.shared.b16 {%0,%1,%2,%3}, [%4];"
        : "=r"(r0), "=r"(r1), "=r"(r2), "=r"(r3) : "r"(addr));
}

__device__ __forceinline__ void ldmx4t(uint32_t& r0, uint32_t& r1,
                                       uint32_t& r2, uint32_t& r3,
                                       uint32_t addr) {
    asm volatile(
        "ldmatrix.sync.aligned.m8n8.x4.trans.shared.b16 {%0,%1,%2,%3}, [%4];"
        : "=r"(r0), "=r"(r1), "=r"(r2), "=r"(r3) : "r"(addr));
}

__device__ __forceinline__ void mma16816(float* c, const uint32_t* a,
                                         const uint32_t* b) {
    asm volatile(
        "mma.sync.aligned.m16n8k16.row.col.f32.bf16.bf16.f32 "
        "{%0,%1,%2,%3}, {%4,%5,%6,%7}, {%8,%9}, {%0,%1,%2,%3};"
        : "+f"(c[0]), "+f"(c[1]), "+f"(c[2]), "+f"(c[3])
        : "r"(a[0]), "r"(a[1]), "r"(a[2]), "r"(a[3]), "r"(b[0]), "r"(b[1]));
}

__device__ __forceinline__ void split2(float x, __nv_bfloat16& h, __nv_bfloat16& l) {
    h = __float2bfloat16_rn(x);
    l = __float2bfloat16_rn(x - __bfloat162float(h));
}

// ============================================================================
// bf16 HMMA GEMM over K3 (verified).
// mode 0: C fp32 = acc + bias;  mode 1: split bf16 hi/lo planes.
// ============================================================================
struct GemmArgs {
    const __nv_bfloat16* A[3];
    const __nv_bfloat16* B[3];
    const float* bias[3];
    float* C[3];
    __nv_bfloat16* Ch[3];
    __nv_bfloat16* Cl[3];
    int mode;
};

#define BK 32
#define RS 40
#define BUFH (128 * RS)

__global__ __launch_bounds__(256) void gemm_mma(GemmArgs ga, int N) {
    __shared__ __align__(16) __nv_bfloat16 As[2][BUFH];
    __shared__ __align__(16) __nv_bfloat16 Bs[2][BUFH];

    const int t = threadIdx.x;
    const int lane = t & 31;
    const int wid = t >> 5;
    const int wm = (wid & 1) * 64;
    const int wn = (wid >> 1) * 32;
    const int grp = lane >> 2;
    const int tig = lane & 3;
    const int z = blockIdx.z;
    const int m0 = blockIdx.y * 128;
    const int n0 = blockIdx.x * 128;

    const __nv_bfloat16* Ag = ga.A[z];
    const __nv_bfloat16* Bg = ga.B[z];
    const float* bias = ga.bias[z];

    const int lrow = t >> 1;
    const int lcol = (t & 1) * 16;
    const __nv_bfloat16* Ap = Ag + (size_t)(m0 + lrow) * K3 + lcol;
    const __nv_bfloat16* Bp = Bg + (size_t)(n0 + lrow) * K3 + lcol;
    const uint32_t sst = lrow * (RS * 2) + lcol * 2;

    const uint32_t asb = smem_u32(As);
    const uint32_t bsb = smem_u32(Bs);

    const uint32_t a_base = asb + (wm + (lane & 15)) * (RS * 2) + ((lane >> 4) * 8) * 2;
    const uint32_t b_base = bsb + (wn + (lane & 7) + ((lane >> 4) & 1) * 8) * (RS * 2) +
                            (((lane >> 3) & 1) * 8) * 2;

    float acc[4][4][4];
#pragma unroll
    for (int mi = 0; mi < 4; ++mi)
#pragma unroll
        for (int ni = 0; ni < 4; ++ni)
#pragma unroll
            for (int r = 0; r < 4; ++r) acc[mi][ni][r] = 0.f;

    uint4 pa0 = *(const uint4*)(Ap);
    uint4 pa1 = *(const uint4*)(Ap + 8);
    uint4 pb0 = *(const uint4*)(Bp);
    uint4 pb1 = *(const uint4*)(Bp + 8);
    *(uint4*)((char*)As + sst)      = pa0;
    *(uint4*)((char*)As + sst + 16) = pa1;
    *(uint4*)((char*)Bs + sst)      = pb0;
    *(uint4*)((char*)Bs + sst + 16) = pb1;
    __syncthreads();

    const int NT = K3 / BK;
    for (int kt = 0; kt < NT; ++kt) {
        const int buf = kt & 1;
        const bool has_next = (kt + 1 < NT);
        if (has_next) {
            const __nv_bfloat16* an = Ap + (size_t)(kt + 1) * BK;
            const __nv_bfloat16* bn = Bp + (size_t)(kt + 1) * BK;
            pa0 = *(const uint4*)(an);
            pa1 = *(const uint4*)(an + 8);
            pb0 = *(const uint4*)(bn);
            pb1 = *(const uint4*)(bn + 8);
        }

        const uint32_t abuf = a_base + buf * (BUFH * 2);
        const uint32_t bbuf = b_base + buf * (BUFH * 2);
#pragma unroll
        for (int ks = 0; ks < 2; ++ks) {
            uint32_t a[4][4], b[4][2];
#pragma unroll
            for (int mi = 0; mi < 4; ++mi)
                ldmx4(a[mi][0], a[mi][1], a[mi][2], a[mi][3],
                      abuf + mi * 16 * (RS * 2) + ks * 32);
#pragma unroll
            for (int nb = 0; nb < 2; ++nb)
                ldmx4(b[nb * 2][0], b[nb * 2][1], b[nb * 2 + 1][0],
                      b[nb * 2 + 1][1],
                      bbuf + nb * 16 * (RS * 2) + ks * 32);
#pragma unroll
            for (int mi = 0; mi < 4; ++mi)
#pragma unroll
                for (int ni = 0; ni < 4; ++ni)
                    mma16816(acc[mi][ni], a[mi], b[ni]);
        }

        if (has_next) {
            const uint32_t nb = (buf ^ 1);
            *(uint4*)((char*)As + nb * (BUFH * 2) + sst)      = pa0;
            *(uint4*)((char*)As + nb * (BUFH * 2) + sst + 16) = pa1;
            *(uint4*)((char*)Bs + nb * (BUFH * 2) + sst)      = pb0;
            *(uint4*)((char*)Bs + nb * (BUFH * 2) + sst + 16) = pb1;
        }
        __syncthreads();
    }

    if (ga.mode == 0) {
        float* C = ga.C[z];
#pragma unroll
        for (int ni = 0; ni < 4; ++ni) {
            const int col = n0 + wn + ni * 8 + tig * 2;
            const float2 bv = *(const float2*)&bias[col];
#pragma unroll
            for (int mi = 0; mi < 4; ++mi) {
                const int row = m0 + wm + mi * 16 + grp;
                *(float2*)&C[(size_t)row * N + col] =
                    make_float2(acc[mi][ni][0] + bv.x, acc[mi][ni][1] + bv.y);
                *(float2*)&C[(size_t)(row + 8) * N + col] =
                    make_float2(acc[mi][ni][2] + bv.x, acc[mi][ni][3] + bv.y);
            }
        }
    } else {
        __nv_bfloat16* Ch = ga.Ch[z];
        __nv_bfloat16* Cl = ga.Cl[z];
#pragma unroll
        for (int ni = 0; ni < 4; ++ni) {
            const int col = n0 + wn + ni * 8 + tig * 2;
            const float2 bv = *(const float2*)&bias[col];
#pragma unroll
            for (int mi = 0; mi < 4; ++mi) {
                const int row = m0 + wm + mi * 16 + grp;
                float f00 = acc[mi][ni][0] + bv.x, f01 = acc[mi][ni][1] + bv.y;
                float f10 = acc[mi][ni][2] + bv.x, f11 = acc[mi][ni][3] + bv.y;
                __nv_bfloat16 h00, l00, h01, l01, h10, l10, h11, l11;
                split2(f00, h00, l00);
                split2(f01, h01, l01);
                split2(f10, h10, l10);
                split2(f11, h11, l11);
                const size_t i0 = (size_t)row * N + col;
                const size_t i1 = (size_t)(row + 8) * N + col;
                *(__nv_bfloat162*)(Ch + i0) = __halves2bfloat162(h00, h01);
                *(__nv_bfloat162*)(Cl + i0) = __halves2bfloat162(l00, l01);
                *(__nv_bfloat162*)(Ch + i1) = __halves2bfloat162(h10, h11);
                *(__nv_bfloat162*)(Cl + i1) = __halves2bfloat162(l10, l11);
            }
        }
    }
}

// ============================================================================
// K prefix-sum kernel: P[bh][row][d] = sum_{k<=row} (Kh+Kl)[b, k, h*64+d]
// grid 32 blocks (one per b,h), 512 threads = 8 chunks x 64 d-lanes.
// ============================================================================
__global__ __launch_bounds__(512) void prefix_kernel(
    const __nv_bfloat16* __restrict__ Khg, const __nv_bfloat16* __restrict__ Klg,
    float* __restrict__ P) {
    const int bh = blockIdx.x;
    const int b = bh >> 4, h = bh & 15;
    const int chunk = threadIdx.x >> 6;      // 0..7
    const int d = threadIdx.x & 63;
    const int CH = SS / 8;                   // 128 rows per chunk
    const size_t inb = (size_t)b * SS * DMOD + (size_t)h * DH + d;
    const size_t outb = (size_t)bh * SS * DH + d;
    const int r0 = chunk * CH;

    float run = 0.f;
    for (int i = 0; i < CH; ++i) {
        const size_t ro = (size_t)(r0 + i) * DMOD;
        run += __bfloat162float(Khg[inb + ro]) + __bfloat162float(Klg[inb + ro]);
        P[outb + (size_t)(r0 + i) * DH] = run;
    }
    __shared__ float tot[8][64];
    tot[chunk][d] = run;
    __syncthreads();
    float off = 0.f;
    for (int c = 0; c < chunk; ++c) off += tot[c][d];
    if (chunk > 0) {
        for (int i = 0; i < CH; ++i)
            P[outb + (size_t)(r0 + i) * DH] += off;
    }
}

// ============================================================================
// Tensor-core fused attention v3: 64-q-tile x 64-k-tile, 256 thr, 2 CTA/SM.
// classSum computed analytically in prologue (prefix sums); hot loop is pure:
// load -> QK^T mma -> (+pp, scale, split-store S) -> S@V mma.
// smem 95232 B.
// ============================================================================
#define QRS 72           // halves per row; 144B
#define ATT_SMEM 95232
#define S32 0.03125f

__global__ __launch_bounds__(256, 2) void attn_mma(
    const __nv_bfloat16* __restrict__ Qhg, const __nv_bfloat16* __restrict__ Qlg,
    const __nv_bfloat16* __restrict__ Khg, const __nv_bfloat16* __restrict__ Klg,
    const __nv_bfloat16* __restrict__ Vhg, const __nv_bfloat16* __restrict__ Vlg,
    const float* __restrict__ Pg,
    const float* __restrict__ rkt, const float* __restrict__ rvt,
    __nv_bfloat16* __restrict__ x2) {
    extern __shared__ char smc[];
    __nv_bfloat16* Qh = (__nv_bfloat16*)(smc);
    __nv_bfloat16* Ql = (__nv_bfloat16*)(smc + 9216);
    __nv_bfloat16* Kh = (__nv_bfloat16*)(smc + 18432);
    __nv_bfloat16* Kl = (__nv_bfloat16*)(smc + 27648);
    __nv_bfloat16* Vh = (__nv_bfloat16*)(smc + 36864);
    __nv_bfloat16* Vl = (__nv_bfloat16*)(smc + 46080);
    __nv_bfloat16* Sh = (__nv_bfloat16*)(smc + 55296);
    __nv_bfloat16* Sl = (__nv_bfloat16*)(smc + 64512);
    float* rk = (float*)(smc + 73728);   // 21*64
    float* rv = (float*)(smc + 79104);   // 21*64
    float* pp = (float*)(smc + 84480);   // 64*21
    float* cs = (float*)(smc + 89856);   // 64*21

    const uint32_t sQh = smem_u32(Qh), sQl = smem_u32(Ql);
    const uint32_t sKh = smem_u32(Kh), sKl = smem_u32(Kl);
    const uint32_t sVh = smem_u32(Vh), sVl = smem_u32(Vl);
    const uint32_t sSh = smem_u32(Sh), sSl = smem_u32(Sl);

    const int t = threadIdx.x;
    const int lane = t & 31;
    const int w = t >> 5;                  // 0..7
    const int grp = lane >> 2;
    const int tig = lane & 3;
    const int q0 = blockIdx.x * 64;
    const int h = blockIdx.y;
    const int b = blockIdx.z;
    const int bh = b * HH + h;
    const size_t hoff = (size_t)h * DH;

    // ---- load Q planes (pure copies) + rk/rv ----
    if (t < 128) {
        const int pl = t >> 6;
        const int r = t & 63;
        const __nv_bfloat16* src =
            (pl ? Qlg : Qhg) + ((size_t)b * SS + q0 + r) * DMOD + hoff;
        __nv_bfloat16* dst = (pl ? Ql : Qh) + r * QRS;
#pragma unroll
        for (int i = 0; i < 8; ++i)
            *(uint4*)(dst + i * 8) = *(const uint4*)(src + i * 8);
    }
    for (int i = t; i < NR * 64; i += 256) { rk[i] = rkt[i]; rv[i] = rvt[i]; }
    __syncthreads();

    // ---- prologue: pp[q][j] and analytic cs[q][j] ----
    for (int e = t; e < 64 * NR; e += 256) {
        const int qq = e / NR, j = e - qq * NR;
        const int gq = q0 + qq;
        // reconstruct Q row into a dot against rk[j]
        float ppv = 0.f;
#pragma unroll 16
        for (int d = 0; d < 64; ++d)
            ppv += (__bfloat162float(Qh[qq * QRS + d]) +
                    __bfloat162float(Ql[qq * QRS + d])) * rk[j * 64 + d];
        pp[e] = ppv;

        float csv = 0.f;
        if (j == 0) {
            const int n0 = gq - 9;                     // count of k <= gq-10
            if (n0 > 0) {
                const float* Pr = Pg + ((size_t)bh * SS + (gq - 10)) * DH;
                float dot = 0.f;
#pragma unroll 16
                for (int d = 0; d < 64; ++d)
                    dot += (__bfloat162float(Qh[qq * QRS + d]) +
                            __bfloat162float(Ql[qq * QRS + d])) * Pr[d];
                csv = (dot + (float)n0 * ppv) * S32;
            }
        } else if (j == 20) {
            const int n20 = SS - gq - 10;              // count of k >= gq+10
            if (n20 > 0) {
                const float* Pr = Pg + ((size_t)bh * SS + (gq + 9)) * DH;
                const float* Pt = Pg + ((size_t)bh * SS + (SS - 1)) * DH;
                float dot = 0.f;
#pragma unroll 16
                for (int d = 0; d < 64; ++d)
                    dot += (__bfloat162float(Qh[qq * QRS + d]) +
                            __bfloat162float(Ql[qq * QRS + d])) * (Pt[d] - Pr[d]);
                csv = (dot + (float)n20 * ppv) * S32;
            }
        } else {
            const int kk = gq + j - 10;
            if (kk >= 0 && kk < SS) {
                const __nv_bfloat16* Krh = Khg + ((size_t)b * SS + kk) * DMOD + hoff;
                const __nv_bfloat16* Krl = Klg + ((size_t)b * SS + kk) * DMOD + hoff;
                float dot = 0.f;
#pragma unroll 16
                for (int d = 0; d < 64; ++d)
                    dot += (__bfloat162float(Qh[qq * QRS + d]) +
                            __bfloat162float(Ql[qq * QRS + d])) *
                           (__bfloat162float(Krh[d]) + __bfloat162float(Krl[d]));
                csv = (dot + ppv) * S32;
            }
        }
        cs[e] = csv;
    }

    float o[4][4];
#pragma unroll
    for (int ni = 0; ni < 4; ++ni)
#pragma unroll
        for (int r = 0; r < 4; ++r) o[ni][r] = 0.f;

    const int wq = w & 1, wk = w >> 1;     // QK^T: 2x4 warps, 32x16 each
    const int wm2 = w & 3, wd = w >> 2;    // S@V: 4x2 warps, 16x32 each

    // K/V plane copy mapping: 4 planes x 64 rows
    const int kvpl = t >> 6;               // 0:Kh 1:Kl 2:Vh 3:Vl
    const int kvr = t & 63;
    const __nv_bfloat16* kvsrc0 =
        (kvpl == 0 ? Khg : kvpl == 1 ? Klg : kvpl == 2 ? Vhg : Vlg) +
        ((size_t)b * SS + kvr) * DMOD + hoff;
    __nv_bfloat16* kvdst =
        (kvpl == 0 ? Kh : kvpl == 1 ? Kl : kvpl == 2 ? Vh : Vl) + kvr * QRS;

    // QK fragment addresses
    const uint32_t a_off = (wq * 32 + (lane & 15)) * (QRS * 2) + ((lane >> 4) * 8) * 2;
    const uint32_t b_off = (wk * 16 + (lane & 7) + ((lane >> 4) & 1) * 8) * (QRS * 2) +
                           (((lane >> 3) & 1) * 8) * 2;
    // SV fragment addresses
    const uint32_t sa_off = (wm2 * 16 + (lane & 15)) * (QRS * 2) + ((lane >> 4) * 8) * 2;
    const uint32_t vb_row = (lane & 7) + ((lane >> 3) & 1) * 8;
    const uint32_t vb_col = (wd * 32 + (lane >> 4) * 8) * 2;

    for (int kt = 0; kt < 16; ++kt) {
        const int k0 = kt * 64;
        __syncthreads();   // prev iter consumed; prologue visible at kt=0

        // ---- load K,V planes ----
        {
            const __nv_bfloat16* src = kvsrc0 + (size_t)k0 * DMOD;
#pragma unroll
            for (int i = 0; i < 8; ++i)
                *(uint4*)(kvdst + i * 8) = *(const uint4*)(src + i * 8);
        }
        __syncthreads();

        // ---- S = Q K^T over 3 split planes ----
        float s[2][2][4];
#pragma unroll
        for (int mi = 0; mi < 2; ++mi)
#pragma unroll
            for (int ni = 0; ni < 2; ++ni)
#pragma unroll
                for (int r = 0; r < 4; ++r) s[mi][ni][r] = 0.f;

        const uint32_t qpl[3] = {sQh, sQl, sQh};
        const uint32_t kpl[3] = {sKh, sKh, sKl};
#pragma unroll
        for (int p = 0; p < 3; ++p) {
#pragma unroll
            for (int ks = 0; ks < 4; ++ks) {
                uint32_t a[2][4], bb[2][2];
#pragma unroll
                for (int mi = 0; mi < 2; ++mi)
                    ldmx4(a[mi][0], a[mi][1], a[mi][2], a[mi][3],
                          qpl[p] + a_off + mi * 16 * (QRS * 2) + ks * 32);
                ldmx4(bb[0][0], bb[0][1], bb[1][0], bb[1][1],
                      kpl[p] + b_off + ks * 32);
#pragma unroll
                for (int mi = 0; mi < 2; ++mi)
#pragma unroll
                    for (int ni = 0; ni < 2; ++ni)
                        mma16816(s[mi][ni], a[mi], bb[ni]);
            }
        }

        // ---- postprocess: +pp[cls], scale, split-store S (no cs work) ----
#pragma unroll
        for (int mi = 0; mi < 2; ++mi) {
#pragma unroll
            for (int half = 0; half < 2; ++half) {
                const int row = wq * 32 + mi * 16 + grp + half * 8;
                const int gq = q0 + row;
                const float* ppr = pp + row * NR;
#pragma unroll
                for (int ni = 0; ni < 2; ++ni) {
                    const int col = wk * 16 + ni * 8 + tig * 2;
                    const int d0 = k0 + col - gq;
                    const int c0 = d0 < -10 ? 0 : (d0 > 10 ? 20 : d0 + 10);
                    const int c1 = (d0 + 1) < -10 ? 0 : ((d0 + 1) > 10 ? 20 : d0 + 11);
                    const float f0 = (s[mi][ni][half * 2 + 0] + ppr[c0]) * S32;
                    const float f1 = (s[mi][ni][half * 2 + 1] + ppr[c1]) * S32;
                    __nv_bfloat16 h0, lo0, h1, lo1;
                    split2(f0, h0, lo0);
                    split2(f1, h1, lo1);
                    *(__nv_bfloat162*)(Sh + row * QRS + col) = __halves2bfloat162(h0, h1);
                    *(__nv_bfloat162*)(Sl + row * QRS + col) = __halves2bfloat162(lo0, lo1);
                }
            }
        }
        __syncthreads();

        // ---- O += S @ V over 3 split planes (V via ldmatrix.trans) ----
        const uint32_t spl[3] = {sSh, sSl, sSh};
        const uint32_t vpl[3] = {sVh, sVh, sVl};
#pragma unroll
        for (int p = 0; p < 3; ++p) {
#pragma unroll
            for (int ks = 0; ks < 4; ++ks) {
                uint32_t a[4], bb[4][2];
                ldmx4(a[0], a[1], a[2], a[3], spl[p] + sa_off + ks * 32);
#pragma unroll
                for (int nb = 0; nb < 2; ++nb)
                    ldmx4t(bb[nb * 2][0], bb[nb * 2][1], bb[nb * 2 + 1][0],
                           bb[nb * 2 + 1][1],
                           vpl[p] + (ks * 16 + vb_row) * (QRS * 2) +
                               vb_col + nb * 32);
#pragma unroll
                for (int ni = 0; ni < 4; ++ni)
                    mma16816(o[ni], a, bb[ni]);
            }
        }
    }
    __syncthreads();

    // ---- epilogue: O += cs @ rel_v_table; write x2 (hi | lo | hi) ----
#pragma unroll
    for (int ni = 0; ni < 4; ++ni) {
#pragma unroll
        for (int half = 0; half < 2; ++half) {
            const int row = wm2 * 16 + grp + half * 8;
            const int col = wd * 32 + ni * 8 + tig * 2;
            float a0 = o[ni][half * 2 + 0];
            float a1 = o[ni][half * 2 + 1];
            const float* csr = cs + row * NR;
#pragma unroll
            for (int j = 0; j < NR; ++j) {
                const float c = csr[j];
                a0 += c * rv[j * 64 + col];
                a1 += c * rv[j * 64 + col + 1];
            }
            __nv_bfloat16 h0, l0b, h1, l1b;
            split2(a0, h0, l0b);
            split2(a1, h1, l1b);
            const size_t base = ((size_t)b * SS + q0 + row) * K3 + hoff + col;
            const __nv_bfloat162 hi2 = __halves2bfloat162(h0, h1);
            *(__nv_bfloat162*)(x2 + base)        = hi2;
            *(__nv_bfloat162*)(x2 + base + 1024) = __halves2bfloat162(l0b, l1b);
            *(__nv_bfloat162*)(x2 + base + 2048) = hi2;
        }
    }
}

// ============================================================================
// launch
// ============================================================================
extern "C" void kernel_launch(void* const* d_in, const int* in_sizes, int n_in,
                              void* d_out, int out_size) {
    const float* q   = (const float*)d_in[0];
    const float* k   = (const float*)d_in[1];
    const float* v   = (const float*)d_in[2];
    const float* Wq  = (const float*)d_in[4];
    const float* bq  = (const float*)d_in[5];
    const float* Wk  = (const float*)d_in[6];
    const float* bk  = (const float*)d_in[7];
    const float* Wv  = (const float*)d_in[8];
    const float* bv  = (const float*)d_in[9];
    const float* W0  = (const float*)d_in[10];
    const float* b0  = (const float*)d_in[11];
    const float* rkt = (const float*)d_in[12];
    const float* rvt = (const float*)d_in[13];

    __nv_bfloat16 *Qh, *Ql, *Kh, *Kl, *Vh, *Vl;
    cudaGetSymbolAddress((void**)&Qh, g_Qh);
    cudaGetSymbolAddress((void**)&Ql, g_Ql);
    cudaGetSymbolAddress((void**)&Kh, g_Kh);
    cudaGetSymbolAddress((void**)&Kl, g_Kl);
    cudaGetSymbolAddress((void**)&Vh, g_Vh);
    cudaGetSymbolAddress((void**)&Vl, g_Vl);
    float* Pp;
    cudaGetSymbolAddress((void**)&Pp, g_P);
    __nv_bfloat16 *q2, *k2, *v2, *x2, *wq2, *wk2, *wv2, *w02;
    cudaGetSymbolAddress((void**)&q2, g_q2);
    cudaGetSymbolAddress((void**)&k2, g_k2);
    cudaGetSymbolAddress((void**)&v2, g_v2);
    cudaGetSymbolAddress((void**)&x2, g_x2);
    cudaGetSymbolAddress((void**)&wq2, g_wq2);
    cudaGetSymbolAddress((void**)&wk2, g_wk2);
    cudaGetSymbolAddress((void**)&wv2, g_wv2);
    cudaGetSymbolAddress((void**)&w02, g_w02);

    const int M = BB * SS;          // 2048
    const int NACT = M * DMOD;
    const int NW = DMOD * DMOD;

    SplitPack ap;
    ap.in[0] = q;  ap.out[0] = q2;
    ap.in[1] = k;  ap.out[1] = k2;
    ap.in[2] = v;  ap.out[2] = v2;
    ap.in[3] = q;  ap.out[3] = q2;   // unused
    split_multi<<<dim3(NACT / 256, 3), 256>>>(ap, NACT, 1);
    SplitPack wp;
    wp.in[0] = Wq; wp.out[0] = wq2;
    wp.in[1] = Wk; wp.out[1] = wk2;
    wp.in[2] = Wv; wp.out[2] = wv2;
    wp.in[3] = W0; wp.out[3] = w02;
    split_multi<<<dim3(NW / 256, 4), 256>>>(wp, NW, 0);

    // fused q/k/v projections -> pre-split bf16 hi/lo planes
    GemmArgs pa;
    pa.A[0] = q2;  pa.A[1] = k2;  pa.A[2] = v2;
    pa.B[0] = wq2; pa.B[1] = wk2; pa.B[2] = wv2;
    pa.bias[0] = bq; pa.bias[1] = bk; pa.bias[2] = bv;
    pa.C[0] = pa.C[1] = pa.C[2] = nullptr;
    pa.Ch[0] = Qh; pa.Ch[1] = Kh; pa.Ch[2] = Vh;
    pa.Cl[0] = Ql; pa.Cl[1] = Kl; pa.Cl[2] = Vl;
    pa.mode = 1;
    gemm_mma<<<dim3(DMOD / 128, M / 128, 3), 256>>>(pa, DMOD);

    // K prefix sums (per b,h)
    prefix_kernel<<<BB * HH, 512>>>(Kh, Kl, Pp);

    // tensor-core fused attention v3
    cudaFuncSetAttribute(attn_mma,
                         cudaFuncAttributeMaxDynamicSharedMemorySize, ATT_SMEM);
    attn_mma<<<dim3(SS / 64, HH, BB), 256, ATT_SMEM>>>(
        Qh, Ql, Kh, Kl, Vh, Vl, Pp, rkt, rvt, x2);

    // output projection (fp32 out)
    GemmArgs oa;
    oa.A[0] = x2;  oa.A[1] = x2;  oa.A[2] = x2;
    oa.B[0] = w02; oa.B[1] = w02; oa.B[2] = w02;
    oa.bias[0] = b0; oa.bias[1] = b0; oa.bias[2] = b0;
    oa.C[0] = (float*)d_out; oa.C[1] = (float*)d_out; oa.C[2] = (float*)d_out;
    oa.Ch[0] = oa.Ch[1] = oa.Ch[2] = nullptr;
    oa.Cl[0] = oa.Cl[1] = oa.Cl[2] = nullptr;
    oa.mode = 0;
    gemm_mma<<<dim3(DMOD / 128, M / 128, 1), 256>>>(oa, DMOD);
}

// round 8
// speedup vs baseline: 1.5007x; 1.5007x over previous
#include <cuda_runtime.h>
#include <cuda_bf16.h>
#include <cstdint>

#define BB 2
#define SS 1024
#define DMOD 1024
#define HH 16
#define DH 64
#define NR 21     // 2*MAX_REL+1
#define K3 3072   // 3 * DMOD (split-concatenated K)

// ============================================================================
// scratch (static device globals: no allocations allowed)
// ============================================================================
__device__ __nv_bfloat16 g_Qh[BB * SS * DMOD];
__device__ __nv_bfloat16 g_Ql[BB * SS * DMOD];
__device__ __nv_bfloat16 g_Kh[BB * SS * DMOD];
__device__ __nv_bfloat16 g_Kl[BB * SS * DMOD];
__device__ __nv_bfloat16 g_Vh[BB * SS * DMOD];
__device__ __nv_bfloat16 g_Vl[BB * SS * DMOD];

__device__ __nv_bfloat16 g_q2[BB * SS * K3];
__device__ __nv_bfloat16 g_k2[BB * SS * K3];
__device__ __nv_bfloat16 g_v2[BB * SS * K3];
__device__ __nv_bfloat16 g_x2[BB * SS * K3];
__device__ __nv_bfloat16 g_wq2[DMOD * K3];
__device__ __nv_bfloat16 g_wk2[DMOD * K3];
__device__ __nv_bfloat16 g_wv2[DMOD * K3];
__device__ __nv_bfloat16 g_w02[DMOD * K3];

// ============================================================================
// batched split kernel: fp32 -> bf16 hi/lo, written K-concatenated.
// ============================================================================
struct SplitPack {
    const float* in[4];
    __nv_bfloat16* out[4];
};

__global__ __launch_bounds__(256) void split_multi(SplitPack p, int n, int is_act) {
    int i = blockIdx.x * blockDim.x + threadIdx.x;
    if (i >= n) return;
    const float* in = p.in[blockIdx.y];
    __nv_bfloat16* out = p.out[blockIdx.y];
    int m = i >> 10;          // K = 1024
    int k = i & 1023;
    float x = in[i];
    __nv_bfloat16 h = __float2bfloat16_rn(x);
    float r = x - __bfloat162float(h);
    __nv_bfloat16 l = __float2bfloat16_rn(r);
    size_t base = (size_t)m * K3 + k;
    out[base] = h;
    if (is_act) {
        out[base + 1024] = l;
        out[base + 2048] = h;
    } else {
        out[base + 1024] = h;
        out[base + 2048] = l;
    }
}

// ============================================================================
// mma.sync helpers
// ============================================================================
__device__ __forceinline__ uint32_t smem_u32(const void* p) {
    uint32_t a;
    asm("{ .reg .u64 t; cvta.to.shared.u64 t, %1; cvt.u32.u64 %0, t; }"
        : "=r"(a) : "l"(p));
    return a;
}

__device__ __forceinline__ void ldmx4(uint32_t& r0, uint32_t& r1,
                                      uint32_t& r2, uint32_t& r3,
                                      uint32_t addr) {
    asm volatile(
        "ldmatrix.sync.aligned.m8n8.x4.shared.b16 {%0,%1,%2,%3}, [%4];"
        : "=r"(r0), "=r"(r1), "=r"(r2), "=r"(r3) : "r"(addr));
}

__device__ __forceinline__ void ldmx4t(uint32_t& r0, uint32_t& r1,
                                       uint32_t& r2, uint32_t& r3,
                                       uint32_t addr) {
    asm volatile(
        "ldmatrix.sync.aligned.m8n8.x4.trans.shared.b16 {%0,%1,%2,%3}, [%4];"
        : "=r"(r0), "=r"(r1), "=r"(r2), "=r"(r3) : "r"(addr));
}

__device__ __forceinline__ void mma16816(float* c, const uint32_t* a,
                                         const uint32_t* b) {
    asm volatile(
        "mma.sync.aligned.m16n8k16.row.col.f32.bf16.bf16.f32 "
        "{%0,%1,%2,%3}, {%4,%5,%6,%7}, {%8,%9}, {%0,%1,%2,%3};"
        : "+f"(c[0]), "+f"(c[1]), "+f"(c[2]), "+f"(c[3])
        : "r"(a[0]), "r"(a[1]), "r"(a[2]), "r"(a[3]), "r"(b[0]), "r"(b[1]));
}

__device__ __forceinline__ void split2(float x, __nv_bfloat16& h, __nv_bfloat16& l) {
    h = __float2bfloat16_rn(x);
    l = __float2bfloat16_rn(x - __bfloat162float(h));
}

// ============================================================================
// bf16 HMMA GEMM over K3 (verified).
// mode 0: C fp32 = acc + bias;  mode 1: split bf16 hi/lo planes.
// ============================================================================
struct GemmArgs {
    const __nv_bfloat16* A[3];
    const __nv_bfloat16* B[3];
    const float* bias[3];
    float* C[3];
    __nv_bfloat16* Ch[3];
    __nv_bfloat16* Cl[3];
    int mode;
};

#define BK 32
#define RS 40
#define BUFH (128 * RS)

__global__ __launch_bounds__(256) void gemm_mma(GemmArgs ga, int N) {
    __shared__ __align__(16) __nv_bfloat16 As[2][BUFH];
    __shared__ __align__(16) __nv_bfloat16 Bs[2][BUFH];

    const int t = threadIdx.x;
    const int lane = t & 31;
    const int wid = t >> 5;
    const int wm = (wid & 1) * 64;
    const int wn = (wid >> 1) * 32;
    const int grp = lane >> 2;
    const int tig = lane & 3;
    const int z = blockIdx.z;
    const int m0 = blockIdx.y * 128;
    const int n0 = blockIdx.x * 128;

    const __nv_bfloat16* Ag = ga.A[z];
    const __nv_bfloat16* Bg = ga.B[z];
    const float* bias = ga.bias[z];

    const int lrow = t >> 1;
    const int lcol = (t & 1) * 16;
    const __nv_bfloat16* Ap = Ag + (size_t)(m0 + lrow) * K3 + lcol;
    const __nv_bfloat16* Bp = Bg + (size_t)(n0 + lrow) * K3 + lcol;
    const uint32_t sst = lrow * (RS * 2) + lcol * 2;

    const uint32_t asb = smem_u32(As);
    const uint32_t bsb = smem_u32(Bs);

    const uint32_t a_base = asb + (wm + (lane & 15)) * (RS * 2) + ((lane >> 4) * 8) * 2;
    const uint32_t b_base = bsb + (wn + (lane & 7) + ((lane >> 4) & 1) * 8) * (RS * 2) +
                            (((lane >> 3) & 1) * 8) * 2;

    float acc[4][4][4];
#pragma unroll
    for (int mi = 0; mi < 4; ++mi)
#pragma unroll
        for (int ni = 0; ni < 4; ++ni)
#pragma unroll
            for (int r = 0; r < 4; ++r) acc[mi][ni][r] = 0.f;

    uint4 pa0 = *(const uint4*)(Ap);
    uint4 pa1 = *(const uint4*)(Ap + 8);
    uint4 pb0 = *(const uint4*)(Bp);
    uint4 pb1 = *(const uint4*)(Bp + 8);
    *(uint4*)((char*)As + sst)      = pa0;
    *(uint4*)((char*)As + sst + 16) = pa1;
    *(uint4*)((char*)Bs + sst)      = pb0;
    *(uint4*)((char*)Bs + sst + 16) = pb1;
    __syncthreads();

    const int NT = K3 / BK;
    for (int kt = 0; kt < NT; ++kt) {
        const int buf = kt & 1;
        const bool has_next = (kt + 1 < NT);
        if (has_next) {
            const __nv_bfloat16* an = Ap + (size_t)(kt + 1) * BK;
            const __nv_bfloat16* bn = Bp + (size_t)(kt + 1) * BK;
            pa0 = *(const uint4*)(an);
            pa1 = *(const uint4*)(an + 8);
            pb0 = *(const uint4*)(bn);
            pb1 = *(const uint4*)(bn + 8);
        }

        const uint32_t abuf = a_base + buf * (BUFH * 2);
        const uint32_t bbuf = b_base + buf * (BUFH * 2);
#pragma unroll
        for (int ks = 0; ks < 2; ++ks) {
            uint32_t a[4][4], b[4][2];
#pragma unroll
            for (int mi = 0; mi < 4; ++mi)
                ldmx4(a[mi][0], a[mi][1], a[mi][2], a[mi][3],
                      abuf + mi * 16 * (RS * 2) + ks * 32);
#pragma unroll
            for (int nb = 0; nb < 2; ++nb)
                ldmx4(b[nb * 2][0], b[nb * 2][1], b[nb * 2 + 1][0],
                      b[nb * 2 + 1][1],
                      bbuf + nb * 16 * (RS * 2) + ks * 32);
#pragma unroll
            for (int mi = 0; mi < 4; ++mi)
#pragma unroll
                for (int ni = 0; ni < 4; ++ni)
                    mma16816(acc[mi][ni], a[mi], b[ni]);
        }

        if (has_next) {
            const uint32_t nb = (buf ^ 1);
            *(uint4*)((char*)As + nb * (BUFH * 2) + sst)      = pa0;
            *(uint4*)((char*)As + nb * (BUFH * 2) + sst + 16) = pa1;
            *(uint4*)((char*)Bs + nb * (BUFH * 2) + sst)      = pb0;
            *(uint4*)((char*)Bs + nb * (BUFH * 2) + sst + 16) = pb1;
        }
        __syncthreads();
    }

    if (ga.mode == 0) {
        float* C = ga.C[z];
#pragma unroll
        for (int ni = 0; ni < 4; ++ni) {
            const int col = n0 + wn + ni * 8 + tig * 2;
            const float2 bv = *(const float2*)&bias[col];
#pragma unroll
            for (int mi = 0; mi < 4; ++mi) {
                const int row = m0 + wm + mi * 16 + grp;
                *(float2*)&C[(size_t)row * N + col] =
                    make_float2(acc[mi][ni][0] + bv.x, acc[mi][ni][1] + bv.y);
                *(float2*)&C[(size_t)(row + 8) * N + col] =
                    make_float2(acc[mi][ni][2] + bv.x, acc[mi][ni][3] + bv.y);
            }
        }
    } else {
        __nv_bfloat16* Ch = ga.Ch[z];
        __nv_bfloat16* Cl = ga.Cl[z];
#pragma unroll
        for (int ni = 0; ni < 4; ++ni) {
            const int col = n0 + wn + ni * 8 + tig * 2;
            const float2 bv = *(const float2*)&bias[col];
#pragma unroll
            for (int mi = 0; mi < 4; ++mi) {
                const int row = m0 + wm + mi * 16 + grp;
                float f00 = acc[mi][ni][0] + bv.x, f01 = acc[mi][ni][1] + bv.y;
                float f10 = acc[mi][ni][2] + bv.x, f11 = acc[mi][ni][3] + bv.y;
                __nv_bfloat16 h00, l00, h01, l01, h10, l10, h11, l11;
                split2(f00, h00, l00);
                split2(f01, h01, l01);
                split2(f10, h10, l10);
                split2(f11, h11, l11);
                const size_t i0 = (size_t)row * N + col;
                const size_t i1 = (size_t)(row + 8) * N + col;
                *(__nv_bfloat162*)(Ch + i0) = __halves2bfloat162(h00, h01);
                *(__nv_bfloat162*)(Cl + i0) = __halves2bfloat162(l00, l01);
                *(__nv_bfloat162*)(Ch + i1) = __halves2bfloat162(h10, h11);
                *(__nv_bfloat162*)(Cl + i1) = __halves2bfloat162(l10, l11);
            }
        }
    }
}

// ============================================================================
// Tensor-core fused attention (R6 structure + coalesced loads + hoisted frags).
// Block = (128-q-tile, h, b), 512 threads (16 warps), 1 CTA/SM.
// ============================================================================
#define QRS 72           // halves per row; 144B
#define SRS 136          // halves per row (S planes); 272B
#define ATT_SMEM 212480

__global__ __launch_bounds__(512) void attn_mma(
    const __nv_bfloat16* __restrict__ Qhg, const __nv_bfloat16* __restrict__ Qlg,
    const __nv_bfloat16* __restrict__ Khg, const __nv_bfloat16* __restrict__ Klg,
    const __nv_bfloat16* __restrict__ Vhg, const __nv_bfloat16* __restrict__ Vlg,
    const float* __restrict__ rkt, const float* __restrict__ rvt,
    __nv_bfloat16* __restrict__ x2) {
    extern __shared__ char smc[];
    __nv_bfloat16* Qh = (__nv_bfloat16*)(smc);
    __nv_bfloat16* Ql = (__nv_bfloat16*)(smc + 18432);
    __nv_bfloat16* Kh = (__nv_bfloat16*)(smc + 36864);
    __nv_bfloat16* Kl = (__nv_bfloat16*)(smc + 55296);
    __nv_bfloat16* Vh = (__nv_bfloat16*)(smc + 73728);
    __nv_bfloat16* Vl = (__nv_bfloat16*)(smc + 92160);
    __nv_bfloat16* Sh = (__nv_bfloat16*)(smc + 110592);
    __nv_bfloat16* Sl = (__nv_bfloat16*)(smc + 145408);
    float* rk = (float*)(smc + 180224);
    float* rv = (float*)(smc + 185600);
    float* pp = (float*)(smc + 190976);
    float* cs = (float*)(smc + 201728);

    const uint32_t sQh = smem_u32(Qh), sQl = smem_u32(Ql);
    const uint32_t sKh = smem_u32(Kh), sKl = smem_u32(Kl);
    const uint32_t sVh = smem_u32(Vh), sVl = smem_u32(Vl);
    const uint32_t sSh = smem_u32(Sh), sSl = smem_u32(Sl);

    const int t = threadIdx.x;
    const int lane = t & 31;
    const int w = t >> 5;
    const int grp = lane >> 2;
    const int tig = lane & 3;
    const int q0 = blockIdx.x * 128;
    const int h = blockIdx.y;
    const int b = blockIdx.z;
    const size_t hoff = (size_t)h * DH;
    const size_t gbase = (size_t)b * SS * DMOD + hoff;

    // coalesced copy mapping: lane -> chunk within row (8 x uint4 per row)
    const int ch = t & 7;          // 16B chunk index in row
    const int r0c = t >> 3;        // 0..63

    // ---- load Q planes (coalesced: warp covers 4 rows in 128B segments) ----
    {
        const __nv_bfloat16* qg[2] = {Qhg + gbase, Qlg + gbase};
        __nv_bfloat16* qs[2] = {Qh, Ql};
#pragma unroll
        for (int i = 0; i < 4; ++i) {
            const int pl = i >> 1;
            const int row = r0c + (i & 1) * 64;
            *(uint4*)(qs[pl] + row * QRS + ch * 8) =
                *(const uint4*)(qg[pl] + (size_t)(q0 + row) * DMOD + ch * 8);
        }
    }
    for (int i = t; i < NR * 64; i += 512) { rk[i] = rkt[i]; rv[i] = rvt[i]; }
    for (int i = t; i < 128 * NR; i += 512) cs[i] = 0.f;
    __syncthreads();

    // ---- pp[q][j] = Q[q].rel_k[j] (Q = Qh + Ql) ----
    for (int e = t; e < 128 * NR; e += 512) {
        int qq = e / NR, j = e - qq * NR;
        float s = 0.f;
#pragma unroll 16
        for (int d = 0; d < 64; ++d)
            s += (__bfloat162float(Qh[qq * QRS + d]) +
                  __bfloat162float(Ql[qq * QRS + d])) * rk[j * 64 + d];
        pp[e] = s;
    }

    float o[4][4];
#pragma unroll
    for (int ni = 0; ni < 4; ++ni)
#pragma unroll
        for (int r = 0; r < 4; ++r) o[ni][r] = 0.f;

    const int wq = w & 3, wk = w >> 2;       // QK^T: 4x4 warps, 32x32 each
    const int wq2 = w >> 1, wd = w & 1;      // S@V: 8x2 warps, 16x32 each

    // K/V coalesced copy bases
    const __nv_bfloat16* kvg[4] = {Khg + gbase, Klg + gbase, Vhg + gbase, Vlg + gbase};
    __nv_bfloat16* kvs[4] = {Kh, Kl, Vh, Vl};

    // fragment addresses
    const uint32_t a_off = (wq * 32 + (lane & 15)) * (QRS * 2) +
                           ((lane >> 4) * 8) * 2;
    const uint32_t b_off =
        (wk * 32 + (lane & 7) + ((lane >> 4) & 1) * 8) * (QRS * 2) +
        (((lane >> 3) & 1) * 8) * 2;
    const uint32_t sa_off = (wq2 * 16 + (lane & 15)) * (SRS * 2) +
                            ((lane >> 4) * 8) * 2;
    const uint32_t vb_row = (lane & 7) + ((lane >> 3) & 1) * 8;
    const uint32_t vb_col = (wd * 32 + (lane >> 4) * 8) * 2;

    for (int kt = 0; kt < 8; ++kt) {
        const int k0 = kt * 128;
        __syncthreads();   // prev iter fully consumed; pp/cs visible at kt=0

        // ---- load K,V planes (coalesced; each i handles 64 rows of plane i>>1) ----
#pragma unroll
        for (int i = 0; i < 8; ++i) {
            const int pl = i >> 1;
            const int row = r0c + (i & 1) * 64;
            *(uint4*)(kvs[pl] + row * QRS + ch * 8) =
                *(const uint4*)(kvg[pl] + (size_t)(k0 + row) * DMOD + ch * 8);
        }
        __syncthreads();

        // ---- S = Q K^T, 3 planes with hoisted fragments ----
        float s[2][4][4];
#pragma unroll
        for (int mi = 0; mi < 2; ++mi)
#pragma unroll
            for (int ni = 0; ni < 4; ++ni)
#pragma unroll
                for (int r = 0; r < 4; ++r) s[mi][ni][r] = 0.f;

#pragma unroll
        for (int ks = 0; ks < 4; ++ks) {
            uint32_t ah[2][4], al[2][4], bh[4][2], bl[4][2];
#pragma unroll
            for (int mi = 0; mi < 2; ++mi) {
                ldmx4(ah[mi][0], ah[mi][1], ah[mi][2], ah[mi][3],
                      sQh + a_off + mi * 16 * (QRS * 2) + ks * 32);
                ldmx4(al[mi][0], al[mi][1], al[mi][2], al[mi][3],
                      sQl + a_off + mi * 16 * (QRS * 2) + ks * 32);
            }
#pragma unroll
            for (int nb = 0; nb < 2; ++nb) {
                ldmx4(bh[nb * 2][0], bh[nb * 2][1], bh[nb * 2 + 1][0],
                      bh[nb * 2 + 1][1],
                      sKh + b_off + nb * 16 * (QRS * 2) + ks * 32);
                ldmx4(bl[nb * 2][0], bl[nb * 2][1], bl[nb * 2 + 1][0],
                      bl[nb * 2 + 1][1],
                      sKl + b_off + nb * 16 * (QRS * 2) + ks * 32);
            }
#pragma unroll
            for (int mi = 0; mi < 2; ++mi)
#pragma unroll
                for (int ni = 0; ni < 4; ++ni) {
                    mma16816(s[mi][ni], ah[mi], bh[ni]);   // Qh.Kh
                    mma16816(s[mi][ni], al[mi], bh[ni]);   // Ql.Kh
                    mma16816(s[mi][ni], ah[mi], bl[ni]);   // Qh.Kl
                }
        }

        // ---- post-process: + pp[cls], scale, classSum, split-store S ----
        float l0[4] = {0.f, 0.f, 0.f, 0.f};
        float l20[4] = {0.f, 0.f, 0.f, 0.f};
#pragma unroll
        for (int mi = 0; mi < 2; ++mi) {
#pragma unroll
            for (int half = 0; half < 2; ++half) {
                const int row = wq * 32 + mi * 16 + grp + half * 8;
                const int gq = q0 + row;
                const float* ppr = pp + row * NR;
                const int li = mi * 2 + half;
#pragma unroll
                for (int ni = 0; ni < 4; ++ni) {
                    const int col = wk * 32 + ni * 8 + tig * 2;
                    const int d0 = k0 + col - gq;
                    const int d1 = d0 + 1;
                    const int c0 = d0 < -10 ? 0 : (d0 > 10 ? 20 : d0 + 10);
                    const int c1 = d1 < -10 ? 0 : (d1 > 10 ? 20 : d1 + 10);
                    const float f0 = (s[mi][ni][half * 2 + 0] + ppr[c0]) * 0.03125f;
                    const float f1 = (s[mi][ni][half * 2 + 1] + ppr[c1]) * 0.03125f;
                    if (d0 <= -10)      l0[li]  += f0;
                    else if (d0 >= 10)  l20[li] += f0;
                    else                cs[row * NR + d0 + 10] += f0;
                    if (d1 <= -10)      l0[li]  += f1;
                    else if (d1 >= 10)  l20[li] += f1;
                    else                cs[row * NR + d1 + 10] += f1;
                    __nv_bfloat16 h0, lo0, h1, lo1;
                    split2(f0, h0, lo0);
                    split2(f1, h1, lo1);
                    *(__nv_bfloat162*)(Sh + row * SRS + col) = __halves2bfloat162(h0, h1);
                    *(__nv_bfloat162*)(Sl + row * SRS + col) = __halves2bfloat162(lo0, lo1);
                }
            }
        }
#pragma unroll
        for (int li = 0; li < 4; ++li) {
            const int row = wq * 32 + (li >> 1) * 16 + grp + (li & 1) * 8;
            atomicAdd(&cs[row * NR + 0], l0[li]);
            atomicAdd(&cs[row * NR + 20], l20[li]);
        }
        __syncthreads();

        // ---- O += S @ V, 3 planes with hoisted fragments ----
#pragma unroll
        for (int ks = 0; ks < 8; ++ks) {
            uint32_t sh_[4], sl_[4], vh[4][2], vl[4][2];
            ldmx4(sh_[0], sh_[1], sh_[2], sh_[3], sSh + sa_off + ks * 32);
            ldmx4(sl_[0], sl_[1], sl_[2], sl_[3], sSl + sa_off + ks * 32);
#pragma unroll
            for (int nb = 0; nb < 2; ++nb) {
                ldmx4t(vh[nb * 2][0], vh[nb * 2][1], vh[nb * 2 + 1][0],
                       vh[nb * 2 + 1][1],
                       sVh + (ks * 16 + vb_row) * (QRS * 2) + vb_col + nb * 32);
                ldmx4t(vl[nb * 2][0], vl[nb * 2][1], vl[nb * 2 + 1][0],
                       vl[nb * 2 + 1][1],
                       sVl + (ks * 16 + vb_row) * (QRS * 2) + vb_col + nb * 32);
            }
#pragma unroll
            for (int ni = 0; ni < 4; ++ni) {
                mma16816(o[ni], sh_, vh[ni]);   // Sh.Vh
                mma16816(o[ni], sl_, vh[ni]);   // Sl.Vh
                mma16816(o[ni], sh_, vl[ni]);   // Sh.Vl
            }
        }
    }
    __syncthreads();   // cs complete

    // ---- epilogue: O += cs @ rel_v_table; write x2 (hi | lo | hi) ----
#pragma unroll
    for (int ni = 0; ni < 4; ++ni) {
#pragma unroll
        for (int half = 0; half < 2; ++half) {
            const int row = wq2 * 16 + grp + half * 8;
            const int col = wd * 32 + ni * 8 + tig * 2;
            float a0 = o[ni][half * 2 + 0];
            float a1 = o[ni][half * 2 + 1];
            const float* csr = cs + row * NR;
#pragma unroll
            for (int j = 0; j < NR; ++j) {
                const float c = csr[j];
                a0 += c * rv[j * 64 + col];
                a1 += c * rv[j * 64 + col + 1];
            }
            __nv_bfloat16 h0, l0b, h1, l1b;
            split2(a0, h0, l0b);
            split2(a1, h1, l1b);
            const size_t base = ((size_t)b * SS + q0 + row) * K3 + hoff + col;
            const __nv_bfloat162 hi2 = __halves2bfloat162(h0, h1);
            *(__nv_bfloat162*)(x2 + base)        = hi2;
            *(__nv_bfloat162*)(x2 + base + 1024) = __halves2bfloat162(l0b, l1b);
            *(__nv_bfloat162*)(x2 + base + 2048) = hi2;
        }
    }
}

// ============================================================================
// launch
// ============================================================================
extern "C" void kernel_launch(void* const* d_in, const int* in_sizes, int n_in,
                              void* d_out, int out_size) {
    const float* q   = (const float*)d_in[0];
    const float* k   = (const float*)d_in[1];
    const float* v   = (const float*)d_in[2];
    const float* Wq  = (const float*)d_in[4];
    const float* bq  = (const float*)d_in[5];
    const float* Wk  = (const float*)d_in[6];
    const float* bk  = (const float*)d_in[7];
    const float* Wv  = (const float*)d_in[8];
    const float* bv  = (const float*)d_in[9];
    const float* W0  = (const float*)d_in[10];
    const float* b0  = (const float*)d_in[11];
    const float* rkt = (const float*)d_in[12];
    const float* rvt = (const float*)d_in[13];

    __nv_bfloat16 *Qh, *Ql, *Kh, *Kl, *Vh, *Vl;
    cudaGetSymbolAddress((void**)&Qh, g_Qh);
    cudaGetSymbolAddress((void**)&Ql, g_Ql);
    cudaGetSymbolAddress((void**)&Kh, g_Kh);
    cudaGetSymbolAddress((void**)&Kl, g_Kl);
    cudaGetSymbolAddress((void**)&Vh, g_Vh);
    cudaGetSymbolAddress((void**)&Vl, g_Vl);
    __nv_bfloat16 *q2, *k2, *v2, *x2, *wq2, *wk2, *wv2, *w02;
    cudaGetSymbolAddress((void**)&q2, g_q2);
    cudaGetSymbolAddress((void**)&k2, g_k2);
    cudaGetSymbolAddress((void**)&v2, g_v2);
    cudaGetSymbolAddress((void**)&x2, g_x2);
    cudaGetSymbolAddress((void**)&wq2, g_wq2);
    cudaGetSymbolAddress((void**)&wk2, g_wk2);
    cudaGetSymbolAddress((void**)&wv2, g_wv2);
    cudaGetSymbolAddress((void**)&w02, g_w02);

    const int M = BB * SS;          // 2048
    const int NACT = M * DMOD;
    const int NW = DMOD * DMOD;

    SplitPack ap;
    ap.in[0] = q;  ap.out[0] = q2;
    ap.in[1] = k;  ap.out[1] = k2;
    ap.in[2] = v;  ap.out[2] = v2;
    ap.in[3] = q;  ap.out[3] = q2;   // unused
    split_multi<<<dim3(NACT / 256, 3), 256>>>(ap, NACT, 1);
    SplitPack wp;
    wp.in[0] = Wq; wp.out[0] = wq2;
    wp.in[1] = Wk; wp.out[1] = wk2;
    wp.in[2] = Wv; wp.out[2] = wv2;
    wp.in[3] = W0; wp.out[3] = w02;
    split_multi<<<dim3(NW / 256, 4), 256>>>(wp, NW, 0);

    // fused q/k/v projections -> pre-split bf16 hi/lo planes
    GemmArgs pa;
    pa.A[0] = q2;  pa.A[1] = k2;  pa.A[2] = v2;
    pa.B[0] = wq2; pa.B[1] = wk2; pa.B[2] = wv2;
    pa.bias[0] = bq; pa.bias[1] = bk; pa.bias[2] = bv;
    pa.C[0] = pa.C[1] = pa.C[2] = nullptr;
    pa.Ch[0] = Qh; pa.Ch[1] = Kh; pa.Ch[2] = Vh;
    pa.Cl[0] = Ql; pa.Cl[1] = Kl; pa.Cl[2] = Vl;
    pa.mode = 1;
    gemm_mma<<<dim3(DMOD / 128, M / 128, 3), 256>>>(pa, DMOD);

    // tensor-core fused attention
    cudaFuncSetAttribute(attn_mma,
                         cudaFuncAttributeMaxDynamicSharedMemorySize, ATT_SMEM);
    attn_mma<<<dim3(SS / 128, HH, BB), 512, ATT_SMEM>>>(
        Qh, Ql, Kh, Kl, Vh, Vl, rkt, rvt, x2);

    // output projection (fp32 out)
    GemmArgs oa;
    oa.A[0] = x2;  oa.A[1] = x2;  oa.A[2] = x2;
    oa.B[0] = w02; oa.B[1] = w02; oa.B[2] = w02;
    oa.bias[0] = b0; oa.bias[1] = b0; oa.bias[2] = b0;
    oa.C[0] = (float*)d_out; oa.C[1] = (float*)d_out; oa.C[2] = (float*)d_out;
    oa.Ch[0] = oa.Ch[1] = oa.Ch[2] = nullptr;
    oa.Cl[0] = oa.Cl[1] = oa.Cl[2] = nullptr;
    oa.mode = 0;
    gemm_mma<<<dim3(DMOD / 128, M / 128, 1), 256>>>(oa, DMOD);
}

// round 10
// speedup vs baseline: 1.5979x; 1.0648x over previous
#include <cuda_runtime.h>
#include <cuda_bf16.h>
#include <cstdint>

#define BB 2
#define SS 1024
#define DMOD 1024
#define HH 16
#define DH 64
#define NR 21     // 2*MAX_REL+1
#define K3 3072   // 3 * DMOD (split-concatenated K)

// ============================================================================
// scratch (static device globals: no allocations allowed)
// ============================================================================
__device__ __nv_bfloat16 g_Qh[BB * SS * DMOD];
__device__ __nv_bfloat16 g_Ql[BB * SS * DMOD];
__device__ __nv_bfloat16 g_Kh[BB * SS * DMOD];
__device__ __nv_bfloat16 g_Kl[BB * SS * DMOD];
__device__ __nv_bfloat16 g_Vh[BB * SS * DMOD];
__device__ __nv_bfloat16 g_Vl[BB * SS * DMOD];

__device__ __nv_bfloat16 g_q2[BB * SS * K3];
__device__ __nv_bfloat16 g_k2[BB * SS * K3];
__device__ __nv_bfloat16 g_v2[BB * SS * K3];
__device__ __nv_bfloat16 g_x2[BB * SS * K3];
__device__ __nv_bfloat16 g_wq2[DMOD * K3];
__device__ __nv_bfloat16 g_wk2[DMOD * K3];
__device__ __nv_bfloat16 g_wv2[DMOD * K3];
__device__ __nv_bfloat16 g_w02[DMOD * K3];

// ============================================================================
// batched split kernel: fp32 -> bf16 hi/lo, written K-concatenated.
// ============================================================================
struct SplitPack {
    const float* in[4];
    __nv_bfloat16* out[4];
};

__global__ __launch_bounds__(256) void split_multi(SplitPack p, int n, int is_act) {
    int i = blockIdx.x * blockDim.x + threadIdx.x;
    if (i >= n) return;
    const float* in = p.in[blockIdx.y];
    __nv_bfloat16* out = p.out[blockIdx.y];
    int m = i >> 10;          // K = 1024
    int k = i & 1023;
    float x = in[i];
    __nv_bfloat16 h = __float2bfloat16_rn(x);
    float r = x - __bfloat162float(h);
    __nv_bfloat16 l = __float2bfloat16_rn(r);
    size_t base = (size_t)m * K3 + k;
    out[base] = h;
    if (is_act) {
        out[base + 1024] = l;
        out[base + 2048] = h;
    } else {
        out[base + 1024] = h;
        out[base + 2048] = l;
    }
}

// ============================================================================
// mma.sync helpers
// ============================================================================
__device__ __forceinline__ uint32_t smem_u32(const void* p) {
    uint32_t a;
    asm("{ .reg .u64 t; cvta.to.shared.u64 t, %1; cvt.u32.u64 %0, t; }"
        : "=r"(a) : "l"(p));
    return a;
}

__device__ __forceinline__ void ldmx4(uint32_t& r0, uint32_t& r1,
                                      uint32_t& r2, uint32_t& r3,
                                      uint32_t addr) {
    asm volatile(
        "ldmatrix.sync.aligned.m8n8.x4.shared.b16 {%0,%1,%2,%3}, [%4];"
        : "=r"(r0), "=r"(r1), "=r"(r2), "=r"(r3) : "r"(addr));
}

__device__ __forceinline__ void ldmx4t(uint32_t& r0, uint32_t& r1,
                                       uint32_t& r2, uint32_t& r3,
                                       uint32_t addr) {
    asm volatile(
        "ldmatrix.sync.aligned.m8n8.x4.trans.shared.b16 {%0,%1,%2,%3}, [%4];"
        : "=r"(r0), "=r"(r1), "=r"(r2), "=r"(r3) : "r"(addr));
}

__device__ __forceinline__ void mma16816(float* c, const uint32_t* a,
                                         const uint32_t* b) {
    asm volatile(
        "mma.sync.aligned.m16n8k16.row.col.f32.bf16.bf16.f32 "
        "{%0,%1,%2,%3}, {%4,%5,%6,%7}, {%8,%9}, {%0,%1,%2,%3};"
        : "+f"(c[0]), "+f"(c[1]), "+f"(c[2]), "+f"(c[3])
        : "r"(a[0]), "r"(a[1]), "r"(a[2]), "r"(a[3]), "r"(b[0]), "r"(b[1]));
}

__device__ __forceinline__ void split2(float x, __nv_bfloat16& h, __nv_bfloat16& l) {
    h = __float2bfloat16_rn(x);
    l = __float2bfloat16_rn(x - __bfloat162float(h));
}

__device__ __forceinline__ uint32_t pack_bf2(__nv_bfloat16 a, __nv_bfloat16 b) {
    __nv_bfloat162 p = __halves2bfloat162(a, b);
    return *(uint32_t*)&p;
}

// ============================================================================
// bf16 HMMA GEMM over K3 (verified).
// mode 0: C fp32 = acc + bias;  mode 1: split bf16 hi/lo planes.
// ============================================================================
struct GemmArgs {
    const __nv_bfloat16* A[3];
    const __nv_bfloat16* B[3];
    const float* bias[3];
    float* C[3];
    __nv_bfloat16* Ch[3];
    __nv_bfloat16* Cl[3];
    int mode;
};

#define BK 32
#define RS 40
#define BUFH (128 * RS)

__global__ __launch_bounds__(256) void gemm_mma(GemmArgs ga, int N) {
    __shared__ __align__(16) __nv_bfloat16 As[2][BUFH];
    __shared__ __align__(16) __nv_bfloat16 Bs[2][BUFH];

    const int t = threadIdx.x;
    const int lane = t & 31;
    const int wid = t >> 5;
    const int wm = (wid & 1) * 64;
    const int wn = (wid >> 1) * 32;
    const int grp = lane >> 2;
    const int tig = lane & 3;
    const int z = blockIdx.z;
    const int m0 = blockIdx.y * 128;
    const int n0 = blockIdx.x * 128;

    const __nv_bfloat16* Ag = ga.A[z];
    const __nv_bfloat16* Bg = ga.B[z];
    const float* bias = ga.bias[z];

    const int lrow = t >> 1;
    const int lcol = (t & 1) * 16;
    const __nv_bfloat16* Ap = Ag + (size_t)(m0 + lrow) * K3 + lcol;
    const __nv_bfloat16* Bp = Bg + (size_t)(n0 + lrow) * K3 + lcol;
    const uint32_t sst = lrow * (RS * 2) + lcol * 2;

    const uint32_t asb = smem_u32(As);
    const uint32_t bsb = smem_u32(Bs);

    const uint32_t a_base = asb + (wm + (lane & 15)) * (RS * 2) + ((lane >> 4) * 8) * 2;
    const uint32_t b_base = bsb + (wn + (lane & 7) + ((lane >> 4) & 1) * 8) * (RS * 2) +
                            (((lane >> 3) & 1) * 8) * 2;

    float acc[4][4][4];
#pragma unroll
    for (int mi = 0; mi < 4; ++mi)
#pragma unroll
        for (int ni = 0; ni < 4; ++ni)
#pragma unroll
            for (int r = 0; r < 4; ++r) acc[mi][ni][r] = 0.f;

    uint4 pa0 = *(const uint4*)(Ap);
    uint4 pa1 = *(const uint4*)(Ap + 8);
    uint4 pb0 = *(const uint4*)(Bp);
    uint4 pb1 = *(const uint4*)(Bp + 8);
    *(uint4*)((char*)As + sst)      = pa0;
    *(uint4*)((char*)As + sst + 16) = pa1;
    *(uint4*)((char*)Bs + sst)      = pb0;
    *(uint4*)((char*)Bs + sst + 16) = pb1;
    __syncthreads();

    const int NT = K3 / BK;
    for (int kt = 0; kt < NT; ++kt) {
        const int buf = kt & 1;
        const bool has_next = (kt + 1 < NT);
        if (has_next) {
            const __nv_bfloat16* an = Ap + (size_t)(kt + 1) * BK;
            const __nv_bfloat16* bn = Bp + (size_t)(kt + 1) * BK;
            pa0 = *(const uint4*)(an);
            pa1 = *(const uint4*)(an + 8);
            pb0 = *(const uint4*)(bn);
            pb1 = *(const uint4*)(bn + 8);
        }

        const uint32_t abuf = a_base + buf * (BUFH * 2);
        const uint32_t bbuf = b_base + buf * (BUFH * 2);
#pragma unroll
        for (int ks = 0; ks < 2; ++ks) {
            uint32_t a[4][4], b[4][2];
#pragma unroll
            for (int mi = 0; mi < 4; ++mi)
                ldmx4(a[mi][0], a[mi][1], a[mi][2], a[mi][3],
                      abuf + mi * 16 * (RS * 2) + ks * 32);
#pragma unroll
            for (int nb = 0; nb < 2; ++nb)
                ldmx4(b[nb * 2][0], b[nb * 2][1], b[nb * 2 + 1][0],
                      b[nb * 2 + 1][1],
                      bbuf + nb * 16 * (RS * 2) + ks * 32);
#pragma unroll
            for (int mi = 0; mi < 4; ++mi)
#pragma unroll
                for (int ni = 0; ni < 4; ++ni)
                    mma16816(acc[mi][ni], a[mi], b[ni]);
        }

        if (has_next) {
            const uint32_t nb = (buf ^ 1);
            *(uint4*)((char*)As + nb * (BUFH * 2) + sst)      = pa0;
            *(uint4*)((char*)As + nb * (BUFH * 2) + sst + 16) = pa1;
            *(uint4*)((char*)Bs + nb * (BUFH * 2) + sst)      = pb0;
            *(uint4*)((char*)Bs + nb * (BUFH * 2) + sst + 16) = pb1;
        }
        __syncthreads();
    }

    if (ga.mode == 0) {
        float* C = ga.C[z];
#pragma unroll
        for (int ni = 0; ni < 4; ++ni) {
            const int col = n0 + wn + ni * 8 + tig * 2;
            const float2 bv = *(const float2*)&bias[col];
#pragma unroll
            for (int mi = 0; mi < 4; ++mi) {
                const int row = m0 + wm + mi * 16 + grp;
                *(float2*)&C[(size_t)row * N + col] =
                    make_float2(acc[mi][ni][0] + bv.x, acc[mi][ni][1] + bv.y);
                *(float2*)&C[(size_t)(row + 8) * N + col] =
                    make_float2(acc[mi][ni][2] + bv.x, acc[mi][ni][3] + bv.y);
            }
        }
    } else {
        __nv_bfloat16* Ch = ga.Ch[z];
        __nv_bfloat16* Cl = ga.Cl[z];
#pragma unroll
        for (int ni = 0; ni < 4; ++ni) {
            const int col = n0 + wn + ni * 8 + tig * 2;
            const float2 bv = *(const float2*)&bias[col];
#pragma unroll
            for (int mi = 0; mi < 4; ++mi) {
                const int row = m0 + wm + mi * 16 + grp;
                float f00 = acc[mi][ni][0] + bv.x, f01 = acc[mi][ni][1] + bv.y;
                float f10 = acc[mi][ni][2] + bv.x, f11 = acc[mi][ni][3] + bv.y;
                __nv_bfloat16 h00, l00, h01, l01, h10, l10, h11, l11;
                split2(f00, h00, l00);
                split2(f01, h01, l01);
                split2(f10, h10, l10);
                split2(f11, h11, l11);
                const size_t i0 = (size_t)row * N + col;
                const size_t i1 = (size_t)(row + 8) * N + col;
                *(__nv_bfloat162*)(Ch + i0) = __halves2bfloat162(h00, h01);
                *(__nv_bfloat162*)(Cl + i0) = __halves2bfloat162(l00, l01);
                *(__nv_bfloat162*)(Ch + i1) = __halves2bfloat162(h10, h11);
                *(__nv_bfloat162*)(Cl + i1) = __halves2bfloat162(l10, l11);
            }
        }
    }
}

// ============================================================================
// Tensor-core fused attention v4 (FA2-style register S).
// 128-q-tile x 64-k-tile, 256 threads (8 warps), 2 CTAs/SM, single wave.
// Warp w owns q-rows [w*16, w*16+16) and the FULL k range:
//   QK^T acc fragments are repacked in registers as S@V A-operands
//   (no S smem, no cross-warp classSum, no atomics).
// smem: Qh 0, Ql 18432, Kh 36864, Kl 46080, Vh 55296, Vl 64512,
//       rk 73728, rv 79104, pp 84480, cs 95232 -> total 105984 B.
// ============================================================================
#define QRS 72           // halves per row; 144B (conflict-free for ldmatrix)
#define ATT_SMEM 105984
#define S32 0.03125f

__global__ __launch_bounds__(256, 2) void attn_mma(
    const __nv_bfloat16* __restrict__ Qhg, const __nv_bfloat16* __restrict__ Qlg,
    const __nv_bfloat16* __restrict__ Khg, const __nv_bfloat16* __restrict__ Klg,
    const __nv_bfloat16* __restrict__ Vhg, const __nv_bfloat16* __restrict__ Vlg,
    const float* __restrict__ rkt, const float* __restrict__ rvt,
    __nv_bfloat16* __restrict__ x2) {
    extern __shared__ char smc[];
    __nv_bfloat16* Qh = (__nv_bfloat16*)(smc);
    __nv_bfloat16* Ql = (__nv_bfloat16*)(smc + 18432);
    __nv_bfloat16* Kh = (__nv_bfloat16*)(smc + 36864);
    __nv_bfloat16* Kl = (__nv_bfloat16*)(smc + 46080);
    __nv_bfloat16* Vh = (__nv_bfloat16*)(smc + 55296);
    __nv_bfloat16* Vl = (__nv_bfloat16*)(smc + 64512);
    float* rk = (float*)(smc + 73728);
    float* rv = (float*)(smc + 79104);
    float* pp = (float*)(smc + 84480);
    float* cs = (float*)(smc + 95232);

    const uint32_t sQh = smem_u32(Qh), sQl = smem_u32(Ql);
    const uint32_t sKh = smem_u32(Kh), sKl = smem_u32(Kl);
    const uint32_t sVh = smem_u32(Vh), sVl = smem_u32(Vl);

    const int t = threadIdx.x;
    const int lane = t & 31;
    const int w = t >> 5;            // 0..7
    const int grp = lane >> 2;
    const int tig = lane & 3;
    const int q0 = blockIdx.x * 128;
    const int h = blockIdx.y;
    const int b = blockIdx.z;
    const size_t hoff = (size_t)h * DH;
    const size_t gbase = (size_t)b * SS * DMOD + hoff;

    const int ch = t & 7;            // 16B chunk in row (coalesced)
    const int r32 = t >> 3;          // 0..31

    // ---- load Q planes (coalesced) + tables; zero cs ----
    {
        const __nv_bfloat16* qg[2] = {Qhg + gbase, Qlg + gbase};
        __nv_bfloat16* qs[2] = {Qh, Ql};
#pragma unroll
        for (int i = 0; i < 8; ++i) {
            const int pl = i >> 2;
            const int row = r32 + (i & 3) * 32;
            *(uint4*)(qs[pl] + row * QRS + ch * 8) =
                *(const uint4*)(qg[pl] + (size_t)(q0 + row) * DMOD + ch * 8);
        }
    }
    for (int i = t; i < NR * 64; i += 256) { rk[i] = rkt[i]; rv[i] = rvt[i]; }
    for (int i = t; i < 128 * NR; i += 256) cs[i] = 0.f;
    __syncthreads();

    // ---- pp[q][j] = Q[q].rel_k[j] (Q = Qh + Ql) ----
    for (int e = t; e < 128 * NR; e += 256) {
        int qq = e / NR, j = e - qq * NR;
        float s = 0.f;
#pragma unroll 16
        for (int d = 0; d < 64; ++d)
            s += (__bfloat162float(Qh[qq * QRS + d]) +
                  __bfloat162float(Ql[qq * QRS + d])) * rk[j * 64 + d];
        pp[e] = s;
    }

    // O accumulators: 8 n-tiles x 4 (rows grp/grp+8, cols ni*8+tig*2)
    float o[8][4];
#pragma unroll
    for (int ni = 0; ni < 8; ++ni)
#pragma unroll
        for (int r = 0; r < 4; ++r) o[ni][r] = 0.f;

    float l0a[2] = {0.f, 0.f};     // clip-class accumulators (rows grp, grp+8)
    float l20a[2] = {0.f, 0.f};

    // fragment addresses
    const uint32_t a_off = (w * 16 + (lane & 15)) * (QRS * 2) + ((lane >> 4) * 8) * 2;
    const uint32_t b_off = ((lane & 7) + ((lane >> 4) & 1) * 8) * (QRS * 2) +
                           (((lane >> 3) & 1) * 8) * 2;
    const uint32_t vb_row = (lane & 7) + ((lane >> 3) & 1) * 8;
    const uint32_t vb_cb  = ((lane >> 4) * 8) * 2;

    // K/V coalesced copy bases (4 planes x 64 rows)
    const __nv_bfloat16* kvg[4] = {Khg + gbase, Klg + gbase, Vhg + gbase, Vlg + gbase};
    __nv_bfloat16* kvs[4] = {Kh, Kl, Vh, Vl};

    for (int kt = 0; kt < 16; ++kt) {
        const int k0 = kt * 64;
        __syncthreads();   // prev iter's K/V fully consumed; pp/cs visible at kt=0

        // ---- load K,V planes (coalesced) ----
#pragma unroll
        for (int i = 0; i < 8; ++i) {
            const int pl = i >> 1;
            const int row = r32 + (i & 1) * 32;
            *(uint4*)(kvs[pl] + row * QRS + ch * 8) =
                *(const uint4*)(kvg[pl] + (size_t)(k0 + row) * DMOD + ch * 8);
        }
        __syncthreads();

        // ---- S = Q K^T (m16 x n64 per warp), 3 split planes ----
        float s[8][4];
#pragma unroll
        for (int ni = 0; ni < 8; ++ni)
#pragma unroll
            for (int r = 0; r < 4; ++r) s[ni][r] = 0.f;

#pragma unroll
        for (int ks = 0; ks < 4; ++ks) {
            uint32_t ah[4], al[4];
            ldmx4(ah[0], ah[1], ah[2], ah[3], sQh + a_off + ks * 32);
            ldmx4(al[0], al[1], al[2], al[3], sQl + a_off + ks * 32);
#pragma unroll
            for (int nb = 0; nb < 4; ++nb) {
                uint32_t kh[4], kl[4];
                ldmx4(kh[0], kh[1], kh[2], kh[3],
                      sKh + b_off + nb * 16 * (QRS * 2) + ks * 32);
                ldmx4(kl[0], kl[1], kl[2], kl[3],
                      sKl + b_off + nb * 16 * (QRS * 2) + ks * 32);
                uint32_t bh0[2] = {kh[0], kh[1]}, bh1[2] = {kh[2], kh[3]};
                uint32_t bl0[2] = {kl[0], kl[1]}, bl1[2] = {kl[2], kl[3]};
                mma16816(s[nb * 2],     ah, bh0);
                mma16816(s[nb * 2],     al, bh0);
                mma16816(s[nb * 2],     ah, bl0);
                mma16816(s[nb * 2 + 1], ah, bh1);
                mma16816(s[nb * 2 + 1], al, bh1);
                mma16816(s[nb * 2 + 1], ah, bl1);
            }
        }

        // ---- postprocess in registers: +pp[cls], scale, classSum, repack ----
        uint32_t ahf[4][4], alf[4][4];   // S@V A-operand fragments (k chunks)
#pragma unroll
        for (int ni = 0; ni < 8; ++ni) {
            const int colg = k0 + ni * 8 + tig * 2;
#pragma unroll
            for (int hf = 0; hf < 2; ++hf) {
                const int row = w * 16 + grp + hf * 8;
                const int gq = q0 + row;
                const float* ppr = pp + row * NR;
                const int d0 = colg - gq;
                const int d1 = d0 + 1;
                const int c0 = d0 < -10 ? 0 : (d0 > 10 ? 20 : d0 + 10);
                const int c1 = d1 < -10 ? 0 : (d1 > 10 ? 20 : d1 + 10);
                const float f0 = (s[ni][hf * 2 + 0] + ppr[c0]) * S32;
                const float f1 = (s[ni][hf * 2 + 1] + ppr[c1]) * S32;
                if (d0 <= -10)      l0a[hf]  += f0;
                else if (d0 >= 10)  l20a[hf] += f0;
                else                cs[row * NR + d0 + 10] += f0;
                if (d1 <= -10)      l0a[hf]  += f1;
                else if (d1 >= 10)  l20a[hf] += f1;
                else                cs[row * NR + d1 + 10] += f1;
                __nv_bfloat16 h0, lo0, h1, lo1;
                split2(f0, h0, lo0);
                split2(f1, h1, lo1);
                const int kc = ni >> 1;
                const int sub = (ni & 1) * 2 + hf;
                ahf[kc][sub] = pack_bf2(h0, h1);
                alf[kc][sub] = pack_bf2(lo0, lo1);
            }
        }

        // ---- O += S @ V from registers (V via ldmatrix.trans), 3 planes ----
#pragma unroll
        for (int kc = 0; kc < 4; ++kc) {
#pragma unroll
            for (int nb = 0; nb < 4; ++nb) {
                uint32_t vh[4], vl[4];
                ldmx4t(vh[0], vh[1], vh[2], vh[3],
                       sVh + (kc * 16 + vb_row) * (QRS * 2) + vb_cb + nb * 32);
                ldmx4t(vl[0], vl[1], vl[2], vl[3],
                       sVl + (kc * 16 + vb_row) * (QRS * 2) + vb_cb + nb * 32);
                uint32_t bh0[2] = {vh[0], vh[1]}, bh1[2] = {vh[2], vh[3]};
                uint32_t bl0[2] = {vl[0], vl[1]}, bl1[2] = {vl[2], vl[3]};
                mma16816(o[nb * 2],     ahf[kc], bh0);
                mma16816(o[nb * 2],     alf[kc], bh0);
                mma16816(o[nb * 2],     ahf[kc], bl0);
                mma16816(o[nb * 2 + 1], ahf[kc], bh1);
                mma16816(o[nb * 2 + 1], alf[kc], bh1);
                mma16816(o[nb * 2 + 1], ahf[kc], bl1);
            }
        }
    }

    // ---- finalize clip classes (warp-local shfl reduce over tig) ----
#pragma unroll
    for (int hf = 0; hf < 2; ++hf) {
        float v0 = l0a[hf];
        v0 += __shfl_xor_sync(0xffffffffu, v0, 1);
        v0 += __shfl_xor_sync(0xffffffffu, v0, 2);
        float v20 = l20a[hf];
        v20 += __shfl_xor_sync(0xffffffffu, v20, 1);
        v20 += __shfl_xor_sync(0xffffffffu, v20, 2);
        if (tig == 0) {
            const int row = w * 16 + grp + hf * 8;
            cs[row * NR + 0]  += v0;
            cs[row * NR + 20] += v20;
        }
    }
    __syncwarp();

    // ---- epilogue: O += cs @ rel_v_table; write x2 (hi | lo | hi) ----
#pragma unroll
    for (int ni = 0; ni < 8; ++ni) {
#pragma unroll
        for (int hf = 0; hf < 2; ++hf) {
            const int row = w * 16 + grp + hf * 8;
            const int col = ni * 8 + tig * 2;
            float a0 = o[ni][hf * 2 + 0];
            float a1 = o[ni][hf * 2 + 1];
            const float* csr = cs + row * NR;
#pragma unroll
            for (int j = 0; j < NR; ++j) {
                const float c = csr[j];
                a0 += c * rv[j * 64 + col];
                a1 += c * rv[j * 64 + col + 1];
            }
            __nv_bfloat16 h0, l0b, h1, l1b;
            split2(a0, h0, l0b);
            split2(a1, h1, l1b);
            const size_t base = ((size_t)b * SS + q0 + row) * K3 + hoff + col;
            const __nv_bfloat162 hi2 = __halves2bfloat162(h0, h1);
            *(__nv_bfloat162*)(x2 + base)        = hi2;
            *(__nv_bfloat162*)(x2 + base + 1024) = __halves2bfloat162(l0b, l1b);
            *(__nv_bfloat162*)(x2 + base + 2048) = hi2;
        }
    }
}

// ============================================================================
// launch
// ============================================================================
extern "C" void kernel_launch(void* const* d_in, const int* in_sizes, int n_in,
                              void* d_out, int out_size) {
    const float* q   = (const float*)d_in[0];
    const float* k   = (const float*)d_in[1];
    const float* v   = (const float*)d_in[2];
    const float* Wq  = (const float*)d_in[4];
    const float* bq  = (const float*)d_in[5];
    const float* Wk  = (const float*)d_in[6];
    const float* bk  = (const float*)d_in[7];
    const float* Wv  = (const float*)d_in[8];
    const float* bv  = (const float*)d_in[9];
    const float* W0  = (const float*)d_in[10];
    const float* b0  = (const float*)d_in[11];
    const float* rkt = (const float*)d_in[12];
    const float* rvt = (const float*)d_in[13];

    __nv_bfloat16 *Qh, *Ql, *Kh, *Kl, *Vh, *Vl;
    cudaGetSymbolAddress((void**)&Qh, g_Qh);
    cudaGetSymbolAddress((void**)&Ql, g_Ql);
    cudaGetSymbolAddress((void**)&Kh, g_Kh);
    cudaGetSymbolAddress((void**)&Kl, g_Kl);
    cudaGetSymbolAddress((void**)&Vh, g_Vh);
    cudaGetSymbolAddress((void**)&Vl, g_Vl);
    __nv_bfloat16 *q2, *k2, *v2, *x2, *wq2, *wk2, *wv2, *w02;
    cudaGetSymbolAddress((void**)&q2, g_q2);
    cudaGetSymbolAddress((void**)&k2, g_k2);
    cudaGetSymbolAddress((void**)&v2, g_v2);
    cudaGetSymbolAddress((void**)&x2, g_x2);
    cudaGetSymbolAddress((void**)&wq2, g_wq2);
    cudaGetSymbolAddress((void**)&wk2, g_wk2);
    cudaGetSymbolAddress((void**)&wv2, g_wv2);
    cudaGetSymbolAddress((void**)&w02, g_w02);

    const int M = BB * SS;          // 2048
    const int NACT = M * DMOD;
    const int NW = DMOD * DMOD;

    SplitPack ap;
    ap.in[0] = q;  ap.out[0] = q2;
    ap.in[1] = k;  ap.out[1] = k2;
    ap.in[2] = v;  ap.out[2] = v2;
    ap.in[3] = q;  ap.out[3] = q2;   // unused
    split_multi<<<dim3(NACT / 256, 3), 256>>>(ap, NACT, 1);
    SplitPack wp;
    wp.in[0] = Wq; wp.out[0] = wq2;
    wp.in[1] = Wk; wp.out[1] = wk2;
    wp.in[2] = Wv; wp.out[2] = wv2;
    wp.in[3] = W0; wp.out[3] = w02;
    split_multi<<<dim3(NW / 256, 4), 256>>>(wp, NW, 0);

    // fused q/k/v projections -> pre-split bf16 hi/lo planes
    GemmArgs pa;
    pa.A[0] = q2;  pa.A[1] = k2;  pa.A[2] = v2;
    pa.B[0] = wq2; pa.B[1] = wk2; pa.B[2] = wv2;
    pa.bias[0] = bq; pa.bias[1] = bk; pa.bias[2] = bv;
    pa.C[0] = pa.C[1] = pa.C[2] = nullptr;
    pa.Ch[0] = Qh; pa.Ch[1] = Kh; pa.Ch[2] = Vh;
    pa.Cl[0] = Ql; pa.Cl[1] = Kl; pa.Cl[2] = Vl;
    pa.mode = 1;
    gemm_mma<<<dim3(DMOD / 128, M / 128, 3), 256>>>(pa, DMOD);

    // tensor-core fused attention v4
    cudaFuncSetAttribute(attn_mma,
                         cudaFuncAttributeMaxDynamicSharedMemorySize, ATT_SMEM);
    attn_mma<<<dim3(SS / 128, HH, BB), 256, ATT_SMEM>>>(
        Qh, Ql, Kh, Kl, Vh, Vl, rkt, rvt, x2);

    // output projection (fp32 out)
    GemmArgs oa;
    oa.A[0] = x2;  oa.A[1] = x2;  oa.A[2] = x2;
    oa.B[0] = w02; oa.B[1] = w02; oa.B[2] = w02;
    oa.bias[0] = b0; oa.bias[1] = b0; oa.bias[2] = b0;
    oa.C[0] = (float*)d_out; oa.C[1] = (float*)d_out; oa.C[2] = (float*)d_out;
    oa.Ch[0] = oa.Ch[1] = oa.Ch[2] = nullptr;
    oa.Cl[0] = oa.Cl[1] = oa.Cl[2] = nullptr;
    oa.mode = 0;
    gemm_mma<<<dim3(DMOD / 128, M / 128, 1), 256>>>(oa, DMOD);
}

// round 12
// speedup vs baseline: 1.9304x; 1.2081x over previous
#include <cuda_runtime.h>
#include <cuda_bf16.h>
#include <cstdint>

#define BB 2
#define SS 1024
#define DMOD 1024
#define HH 16
#define DH 64
#define NR 21     // 2*MAX_REL+1
#define K3 3072   // 3 * DMOD (split-concatenated K)

// ============================================================================
// scratch (static device globals: no allocations allowed)
// ============================================================================
__device__ __nv_bfloat16 g_Qh[BB * SS * DMOD];
__device__ __nv_bfloat16 g_Ql[BB * SS * DMOD];
__device__ __nv_bfloat16 g_Kh[BB * SS * DMOD];
__device__ __nv_bfloat16 g_Kl[BB * SS * DMOD];
__device__ __nv_bfloat16 g_Vh[BB * SS * DMOD];
__device__ __nv_bfloat16 g_Vl[BB * SS * DMOD];

__device__ __nv_bfloat16 g_q2[BB * SS * K3];
__device__ __nv_bfloat16 g_k2[BB * SS * K3];
__device__ __nv_bfloat16 g_v2[BB * SS * K3];
__device__ __nv_bfloat16 g_x2[BB * SS * K3];
__device__ __nv_bfloat16 g_wq2[DMOD * K3];
__device__ __nv_bfloat16 g_wk2[DMOD * K3];
__device__ __nv_bfloat16 g_wv2[DMOD * K3];
__device__ __nv_bfloat16 g_w02[DMOD * K3];

// ============================================================================
// batched split kernel: fp32 -> bf16 hi/lo, written K-concatenated.
// ============================================================================
struct SplitPack {
    const float* in[4];
    __nv_bfloat16* out[4];
};

__global__ __launch_bounds__(256) void split_multi(SplitPack p, int n, int is_act) {
    int i = blockIdx.x * blockDim.x + threadIdx.x;
    if (i >= n) return;
    const float* in = p.in[blockIdx.y];
    __nv_bfloat16* out = p.out[blockIdx.y];
    int m = i >> 10;          // K = 1024
    int k = i & 1023;
    float x = in[i];
    __nv_bfloat16 h = __float2bfloat16_rn(x);
    float r = x - __bfloat162float(h);
    __nv_bfloat16 l = __float2bfloat16_rn(r);
    size_t base = (size_t)m * K3 + k;
    out[base] = h;
    if (is_act) {
        out[base + 1024] = l;
        out[base + 2048] = h;
    } else {
        out[base + 1024] = h;
        out[base + 2048] = l;
    }
}

// ============================================================================
// mma.sync / cp.async helpers
// ============================================================================
__device__ __forceinline__ uint32_t smem_u32(const void* p) {
    uint32_t a;
    asm("{ .reg .u64 t; cvta.to.shared.u64 t, %1; cvt.u32.u64 %0, t; }"
        : "=r"(a) : "l"(p));
    return a;
}

#define CP_ASYNC16(dst, src) \
    asm volatile("cp.async.cg.shared.global [%0], [%1], 16;" \
                 :: "r"(dst), "l"(src) : "memory")
#define CP_COMMIT() asm volatile("cp.async.commit_group;" ::: "memory")
#define CP_WAIT0()  asm volatile("cp.async.wait_group 0;" ::: "memory")
#define CP_WAIT1()  asm volatile("cp.async.wait_group 1;" ::: "memory")

__device__ __forceinline__ void ldmx4(uint32_t& r0, uint32_t& r1,
                                      uint32_t& r2, uint32_t& r3,
                                      uint32_t addr) {
    asm volatile(
        "ldmatrix.sync.aligned.m8n8.x4.shared.b16 {%0,%1,%2,%3}, [%4];"
        : "=r"(r0), "=r"(r1), "=r"(r2), "=r"(r3) : "r"(addr));
}

__device__ __forceinline__ void ldmx4t(uint32_t& r0, uint32_t& r1,
                                       uint32_t& r2, uint32_t& r3,
                                       uint32_t addr) {
    asm volatile(
        "ldmatrix.sync.aligned.m8n8.x4.trans.shared.b16 {%0,%1,%2,%3}, [%4];"
        : "=r"(r0), "=r"(r1), "=r"(r2), "=r"(r3) : "r"(addr));
}

__device__ __forceinline__ void mma16816(float* c, const uint32_t* a,
                                         const uint32_t* b) {
    asm volatile(
        "mma.sync.aligned.m16n8k16.row.col.f32.bf16.bf16.f32 "
        "{%0,%1,%2,%3}, {%4,%5,%6,%7}, {%8,%9}, {%0,%1,%2,%3};"
        : "+f"(c[0]), "+f"(c[1]), "+f"(c[2]), "+f"(c[3])
        : "r"(a[0]), "r"(a[1]), "r"(a[2]), "r"(a[3]), "r"(b[0]), "r"(b[1]));
}

__device__ __forceinline__ void split2(float x, __nv_bfloat16& h, __nv_bfloat16& l) {
    h = __float2bfloat16_rn(x);
    l = __float2bfloat16_rn(x - __bfloat162float(h));
}

__device__ __forceinline__ uint32_t pack_bf2(__nv_bfloat16 a, __nv_bfloat16 b) {
    __nv_bfloat162 p = __halves2bfloat162(a, b);
    return *(uint32_t*)&p;
}

// ============================================================================
// bf16 HMMA GEMM over K3, cp.async double-buffered, 2 CTAs/SM.
// mode 0: C fp32 = acc + bias;  mode 1: split bf16 hi/lo planes.
// ============================================================================
struct GemmArgs {
    const __nv_bfloat16* A[3];
    const __nv_bfloat16* B[3];
    const float* bias[3];
    float* C[3];
    __nv_bfloat16* Ch[3];
    __nv_bfloat16* Cl[3];
    int mode;
};

#define BK 32
#define RS 40
#define BUFH (128 * RS)

__global__ __launch_bounds__(256, 2) void gemm_mma(GemmArgs ga, int N) {
    __shared__ __align__(16) __nv_bfloat16 As[2][BUFH];
    __shared__ __align__(16) __nv_bfloat16 Bs[2][BUFH];

    const int t = threadIdx.x;
    const int lane = t & 31;
    const int wid = t >> 5;
    const int wm = (wid & 1) * 64;
    const int wn = (wid >> 1) * 32;
    const int grp = lane >> 2;
    const int tig = lane & 3;
    const int z = blockIdx.z;
    const int m0 = blockIdx.y * 128;
    const int n0 = blockIdx.x * 128;

    const __nv_bfloat16* Ag = ga.A[z];
    const __nv_bfloat16* Bg = ga.B[z];
    const float* bias = ga.bias[z];

    const int lrow = t >> 1;
    const int lcol = (t & 1) * 16;
    const __nv_bfloat16* Ap = Ag + (size_t)(m0 + lrow) * K3 + lcol;
    const __nv_bfloat16* Bp = Bg + (size_t)(n0 + lrow) * K3 + lcol;
    const uint32_t sst = lrow * (RS * 2) + lcol * 2;

    const uint32_t asb = smem_u32(As);
    const uint32_t bsb = smem_u32(Bs);

    const uint32_t a_base = asb + (wm + (lane & 15)) * (RS * 2) + ((lane >> 4) * 8) * 2;
    const uint32_t b_base = bsb + (wn + (lane & 7) + ((lane >> 4) & 1) * 8) * (RS * 2) +
                            (((lane >> 3) & 1) * 8) * 2;

    float acc[4][4][4];
#pragma unroll
    for (int mi = 0; mi < 4; ++mi)
#pragma unroll
        for (int ni = 0; ni < 4; ++ni)
#pragma unroll
            for (int r = 0; r < 4; ++r) acc[mi][ni][r] = 0.f;

    // prologue: async-load tile 0 into buf 0
    CP_ASYNC16(asb + sst,      Ap);
    CP_ASYNC16(asb + sst + 16, Ap + 8);
    CP_ASYNC16(bsb + sst,      Bp);
    CP_ASYNC16(bsb + sst + 16, Bp + 8);
    CP_COMMIT();

    const int NT = K3 / BK;
    for (int kt = 0; kt < NT; ++kt) {
        const int buf = kt & 1;
        const bool has_next = (kt + 1 < NT);
        if (has_next) {
            // buf^1 was fully consumed at iter kt-1 (guarded by its trailing sync)
            const uint32_t nb = (buf ^ 1) * (BUFH * 2);
            const __nv_bfloat16* an = Ap + (size_t)(kt + 1) * BK;
            const __nv_bfloat16* bn = Bp + (size_t)(kt + 1) * BK;
            CP_ASYNC16(asb + nb + sst,      an);
            CP_ASYNC16(asb + nb + sst + 16, an + 8);
            CP_ASYNC16(bsb + nb + sst,      bn);
            CP_ASYNC16(bsb + nb + sst + 16, bn + 8);
            CP_COMMIT();
            CP_WAIT1();   // current buf's group done; next may still fly
        } else {
            CP_WAIT0();
        }
        __syncthreads();

        const uint32_t abuf = a_base + buf * (BUFH * 2);
        const uint32_t bbuf = b_base + buf * (BUFH * 2);
#pragma unroll
        for (int ks = 0; ks < 2; ++ks) {
            uint32_t a[4][4], b[4][2];
#pragma unroll
            for (int mi = 0; mi < 4; ++mi)
                ldmx4(a[mi][0], a[mi][1], a[mi][2], a[mi][3],
                      abuf + mi * 16 * (RS * 2) + ks * 32);
#pragma unroll
            for (int nb2 = 0; nb2 < 2; ++nb2)
                ldmx4(b[nb2 * 2][0], b[nb2 * 2][1], b[nb2 * 2 + 1][0],
                      b[nb2 * 2 + 1][1],
                      bbuf + nb2 * 16 * (RS * 2) + ks * 32);
#pragma unroll
            for (int mi = 0; mi < 4; ++mi)
#pragma unroll
                for (int ni = 0; ni < 4; ++ni)
                    mma16816(acc[mi][ni], a[mi], b[ni]);
        }
        __syncthreads();   // all reads of buf done before kt+1 overwrites it
    }

    if (ga.mode == 0) {
        float* C = ga.C[z];
#pragma unroll
        for (int ni = 0; ni < 4; ++ni) {
            const int col = n0 + wn + ni * 8 + tig * 2;
            const float2 bv = *(const float2*)&bias[col];
#pragma unroll
            for (int mi = 0; mi < 4; ++mi) {
                const int row = m0 + wm + mi * 16 + grp;
                *(float2*)&C[(size_t)row * N + col] =
                    make_float2(acc[mi][ni][0] + bv.x, acc[mi][ni][1] + bv.y);
                *(float2*)&C[(size_t)(row + 8) * N + col] =
                    make_float2(acc[mi][ni][2] + bv.x, acc[mi][ni][3] + bv.y);
            }
        }
    } else {
        __nv_bfloat16* Ch = ga.Ch[z];
        __nv_bfloat16* Cl = ga.Cl[z];
#pragma unroll
        for (int ni = 0; ni < 4; ++ni) {
            const int col = n0 + wn + ni * 8 + tig * 2;
            const float2 bv = *(const float2*)&bias[col];
#pragma unroll
            for (int mi = 0; mi < 4; ++mi) {
                const int row = m0 + wm + mi * 16 + grp;
                float f00 = acc[mi][ni][0] + bv.x, f01 = acc[mi][ni][1] + bv.y;
                float f10 = acc[mi][ni][2] + bv.x, f11 = acc[mi][ni][3] + bv.y;
                __nv_bfloat16 h00, l00, h01, l01, h10, l10, h11, l11;
                split2(f00, h00, l00);
                split2(f01, h01, l01);
                split2(f10, h10, l10);
                split2(f11, h11, l11);
                const size_t i0 = (size_t)row * N + col;
                const size_t i1 = (size_t)(row + 8) * N + col;
                *(__nv_bfloat162*)(Ch + i0) = __halves2bfloat162(h00, h01);
                *(__nv_bfloat162*)(Cl + i0) = __halves2bfloat162(l00, l01);
                *(__nv_bfloat162*)(Ch + i1) = __halves2bfloat162(h10, h11);
                *(__nv_bfloat162*)(Cl + i1) = __halves2bfloat162(l10, l11);
            }
        }
    }
}

// ============================================================================
// Tensor-core fused attention v4 (FA2-style register S) — unchanged from R10.
// ============================================================================
#define QRS 72           // halves per row; 144B (conflict-free for ldmatrix)
#define ATT_SMEM 105984
#define S32 0.03125f

__global__ __launch_bounds__(256, 2) void attn_mma(
    const __nv_bfloat16* __restrict__ Qhg, const __nv_bfloat16* __restrict__ Qlg,
    const __nv_bfloat16* __restrict__ Khg, const __nv_bfloat16* __restrict__ Klg,
    const __nv_bfloat16* __restrict__ Vhg, const __nv_bfloat16* __restrict__ Vlg,
    const float* __restrict__ rkt, const float* __restrict__ rvt,
    __nv_bfloat16* __restrict__ x2) {
    extern __shared__ char smc[];
    __nv_bfloat16* Qh = (__nv_bfloat16*)(smc);
    __nv_bfloat16* Ql = (__nv_bfloat16*)(smc + 18432);
    __nv_bfloat16* Kh = (__nv_bfloat16*)(smc + 36864);
    __nv_bfloat16* Kl = (__nv_bfloat16*)(smc + 46080);
    __nv_bfloat16* Vh = (__nv_bfloat16*)(smc + 55296);
    __nv_bfloat16* Vl = (__nv_bfloat16*)(smc + 64512);
    float* rk = (float*)(smc + 73728);
    float* rv = (float*)(smc + 79104);
    float* pp = (float*)(smc + 84480);
    float* cs = (float*)(smc + 95232);

    const uint32_t sQh = smem_u32(Qh), sQl = smem_u32(Ql);
    const uint32_t sKh = smem_u32(Kh), sKl = smem_u32(Kl);
    const uint32_t sVh = smem_u32(Vh), sVl = smem_u32(Vl);

    const int t = threadIdx.x;
    const int lane = t & 31;
    const int w = t >> 5;
    const int grp = lane >> 2;
    const int tig = lane & 3;
    const int q0 = blockIdx.x * 128;
    const int h = blockIdx.y;
    const int b = blockIdx.z;
    const size_t hoff = (size_t)h * DH;
    const size_t gbase = (size_t)b * SS * DMOD + hoff;

    const int ch = t & 7;
    const int r32 = t >> 3;

    {
        const __nv_bfloat16* qg[2] = {Qhg + gbase, Qlg + gbase};
        __nv_bfloat16* qs[2] = {Qh, Ql};
#pragma unroll
        for (int i = 0; i < 8; ++i) {
            const int pl = i >> 2;
            const int row = r32 + (i & 3) * 32;
            *(uint4*)(qs[pl] + row * QRS + ch * 8) =
                *(const uint4*)(qg[pl] + (size_t)(q0 + row) * DMOD + ch * 8);
        }
    }
    for (int i = t; i < NR * 64; i += 256) { rk[i] = rkt[i]; rv[i] = rvt[i]; }
    for (int i = t; i < 128 * NR; i += 256) cs[i] = 0.f;
    __syncthreads();

    for (int e = t; e < 128 * NR; e += 256) {
        int qq = e / NR, j = e - qq * NR;
        float s = 0.f;
#pragma unroll 16
        for (int d = 0; d < 64; ++d)
            s += (__bfloat162float(Qh[qq * QRS + d]) +
                  __bfloat162float(Ql[qq * QRS + d])) * rk[j * 64 + d];
        pp[e] = s;
    }

    float o[8][4];
#pragma unroll
    for (int ni = 0; ni < 8; ++ni)
#pragma unroll
        for (int r = 0; r < 4; ++r) o[ni][r] = 0.f;

    float l0a[2] = {0.f, 0.f};
    float l20a[2] = {0.f, 0.f};

    const uint32_t a_off = (w * 16 + (lane & 15)) * (QRS * 2) + ((lane >> 4) * 8) * 2;
    const uint32_t b_off = ((lane & 7) + ((lane >> 4) & 1) * 8) * (QRS * 2) +
                           (((lane >> 3) & 1) * 8) * 2;
    const uint32_t vb_row = (lane & 7) + ((lane >> 3) & 1) * 8;
    const uint32_t vb_cb  = ((lane >> 4) * 8) * 2;

    const __nv_bfloat16* kvg[4] = {Khg + gbase, Klg + gbase, Vhg + gbase, Vlg + gbase};
    __nv_bfloat16* kvs[4] = {Kh, Kl, Vh, Vl};

    for (int kt = 0; kt < 16; ++kt) {
        const int k0 = kt * 64;
        __syncthreads();

#pragma unroll
        for (int i = 0; i < 8; ++i) {
            const int pl = i >> 1;
            const int row = r32 + (i & 1) * 32;
            *(uint4*)(kvs[pl] + row * QRS + ch * 8) =
                *(const uint4*)(kvg[pl] + (size_t)(k0 + row) * DMOD + ch * 8);
        }
        __syncthreads();

        float s[8][4];
#pragma unroll
        for (int ni = 0; ni < 8; ++ni)
#pragma unroll
            for (int r = 0; r < 4; ++r) s[ni][r] = 0.f;

#pragma unroll
        for (int ks = 0; ks < 4; ++ks) {
            uint32_t ah[4], al[4];
            ldmx4(ah[0], ah[1], ah[2], ah[3], sQh + a_off + ks * 32);
            ldmx4(al[0], al[1], al[2], al[3], sQl + a_off + ks * 32);
#pragma unroll
            for (int nb = 0; nb < 4; ++nb) {
                uint32_t kh[4], kl[4];
                ldmx4(kh[0], kh[1], kh[2], kh[3],
                      sKh + b_off + nb * 16 * (QRS * 2) + ks * 32);
                ldmx4(kl[0], kl[1], kl[2], kl[3],
                      sKl + b_off + nb * 16 * (QRS * 2) + ks * 32);
                uint32_t bh0[2] = {kh[0], kh[1]}, bh1[2] = {kh[2], kh[3]};
                uint32_t bl0[2] = {kl[0], kl[1]}, bl1[2] = {kl[2], kl[3]};
                mma16816(s[nb * 2],     ah, bh0);
                mma16816(s[nb * 2],     al, bh0);
                mma16816(s[nb * 2],     ah, bl0);
                mma16816(s[nb * 2 + 1], ah, bh1);
                mma16816(s[nb * 2 + 1], al, bh1);
                mma16816(s[nb * 2 + 1], ah, bl1);
            }
        }

        uint32_t ahf[4][4], alf[4][4];
#pragma unroll
        for (int ni = 0; ni < 8; ++ni) {
            const int colg = k0 + ni * 8 + tig * 2;
#pragma unroll
            for (int hf = 0; hf < 2; ++hf) {
                const int row = w * 16 + grp + hf * 8;
                const int gq = q0 + row;
                const float* ppr = pp + row * NR;
                const int d0 = colg - gq;
                const int d1 = d0 + 1;
                const int c0 = d0 < -10 ? 0 : (d0 > 10 ? 20 : d0 + 10);
                const int c1 = d1 < -10 ? 0 : (d1 > 10 ? 20 : d1 + 10);
                const float f0 = (s[ni][hf * 2 + 0] + ppr[c0]) * S32;
                const float f1 = (s[ni][hf * 2 + 1] + ppr[c1]) * S32;
                if (d0 <= -10)      l0a[hf]  += f0;
                else if (d0 >= 10)  l20a[hf] += f0;
                else                cs[row * NR + d0 + 10] += f0;
                if (d1 <= -10)      l0a[hf]  += f1;
                else if (d1 >= 10)  l20a[hf] += f1;
                else                cs[row * NR + d1 + 10] += f1;
                __nv_bfloat16 h0, lo0, h1, lo1;
                split2(f0, h0, lo0);
                split2(f1, h1, lo1);
                const int kc = ni >> 1;
                const int sub = (ni & 1) * 2 + hf;
                ahf[kc][sub] = pack_bf2(h0, h1);
                alf[kc][sub] = pack_bf2(lo0, lo1);
            }
        }

#pragma unroll
        for (int kc = 0; kc < 4; ++kc) {
#pragma unroll
            for (int nb = 0; nb < 4; ++nb) {
                uint32_t vh[4], vl[4];
                ldmx4t(vh[0], vh[1], vh[2], vh[3],
                       sVh + (kc * 16 + vb_row) * (QRS * 2) + vb_cb + nb * 32);
                ldmx4t(vl[0], vl[1], vl[2], vl[3],
                       sVl + (kc * 16 + vb_row) * (QRS * 2) + vb_cb + nb * 32);
                uint32_t bh0[2] = {vh[0], vh[1]}, bh1[2] = {vh[2], vh[3]};
                uint32_t bl0[2] = {vl[0], vl[1]}, bl1[2] = {vl[2], vl[3]};
                mma16816(o[nb * 2],     ahf[kc], bh0);
                mma16816(o[nb * 2],     alf[kc], bh0);
                mma16816(o[nb * 2],     ahf[kc], bl0);
                mma16816(o[nb * 2 + 1], ahf[kc], bh1);
                mma16816(o[nb * 2 + 1], alf[kc], bh1);
                mma16816(o[nb * 2 + 1], ahf[kc], bl1);
            }
        }
    }

#pragma unroll
    for (int hf = 0; hf < 2; ++hf) {
        float v0 = l0a[hf];
        v0 += __shfl_xor_sync(0xffffffffu, v0, 1);
        v0 += __shfl_xor_sync(0xffffffffu, v0, 2);
        float v20 = l20a[hf];
        v20 += __shfl_xor_sync(0xffffffffu, v20, 1);
        v20 += __shfl_xor_sync(0xffffffffu, v20, 2);
        if (tig == 0) {
            const int row = w * 16 + grp + hf * 8;
            cs[row * NR + 0]  += v0;
            cs[row * NR + 20] += v20;
        }
    }
    __syncwarp();

#pragma unroll
    for (int ni = 0; ni < 8; ++ni) {
#pragma unroll
        for (int hf = 0; hf < 2; ++hf) {
            const int row = w * 16 + grp + hf * 8;
            const int col = ni * 8 + tig * 2;
            float a0 = o[ni][hf * 2 + 0];
            float a1 = o[ni][hf * 2 + 1];
            const float* csr = cs + row * NR;
#pragma unroll
            for (int j = 0; j < NR; ++j) {
                const float c = csr[j];
                a0 += c * rv[j * 64 + col];
                a1 += c * rv[j * 64 + col + 1];
            }
            __nv_bfloat16 h0, l0b, h1, l1b;
            split2(a0, h0, l0b);
            split2(a1, h1, l1b);
            const size_t base = ((size_t)b * SS + q0 + row) * K3 + hoff + col;
            const __nv_bfloat162 hi2 = __halves2bfloat162(h0, h1);
            *(__nv_bfloat162*)(x2 + base)        = hi2;
            *(__nv_bfloat162*)(x2 + base + 1024) = __halves2bfloat162(l0b, l1b);
            *(__nv_bfloat162*)(x2 + base + 2048) = hi2;
        }
    }
}

// ============================================================================
// launch
// ============================================================================
extern "C" void kernel_launch(void* const* d_in, const int* in_sizes, int n_in,
                              void* d_out, int out_size) {
    const float* q   = (const float*)d_in[0];
    const float* k   = (const float*)d_in[1];
    const float* v   = (const float*)d_in[2];
    const float* Wq  = (const float*)d_in[4];
    const float* bq  = (const float*)d_in[5];
    const float* Wk  = (const float*)d_in[6];
    const float* bk  = (const float*)d_in[7];
    const float* Wv  = (const float*)d_in[8];
    const float* bv  = (const float*)d_in[9];
    const float* W0  = (const float*)d_in[10];
    const float* b0  = (const float*)d_in[11];
    const float* rkt = (const float*)d_in[12];
    const float* rvt = (const float*)d_in[13];

    __nv_bfloat16 *Qh, *Ql, *Kh, *Kl, *Vh, *Vl;
    cudaGetSymbolAddress((void**)&Qh, g_Qh);
    cudaGetSymbolAddress((void**)&Ql, g_Ql);
    cudaGetSymbolAddress((void**)&Kh, g_Kh);
    cudaGetSymbolAddress((void**)&Kl, g_Kl);
    cudaGetSymbolAddress((void**)&Vh, g_Vh);
    cudaGetSymbolAddress((void**)&Vl, g_Vl);
    __nv_bfloat16 *q2, *k2, *v2, *x2, *wq2, *wk2, *wv2, *w02;
    cudaGetSymbolAddress((void**)&q2, g_q2);
    cudaGetSymbolAddress((void**)&k2, g_k2);
    cudaGetSymbolAddress((void**)&v2, g_v2);
    cudaGetSymbolAddress((void**)&x2, g_x2);
    cudaGetSymbolAddress((void**)&wq2, g_wq2);
    cudaGetSymbolAddress((void**)&wk2, g_wk2);
    cudaGetSymbolAddress((void**)&wv2, g_wv2);
    cudaGetSymbolAddress((void**)&w02, g_w02);

    const int M = BB * SS;          // 2048
    const int NACT = M * DMOD;
    const int NW = DMOD * DMOD;

    SplitPack ap;
    ap.in[0] = q;  ap.out[0] = q2;
    ap.in[1] = k;  ap.out[1] = k2;
    ap.in[2] = v;  ap.out[2] = v2;
    ap.in[3] = q;  ap.out[3] = q2;   // unused
    split_multi<<<dim3(NACT / 256, 3), 256>>>(ap, NACT, 1);
    SplitPack wp;
    wp.in[0] = Wq; wp.out[0] = wq2;
    wp.in[1] = Wk; wp.out[1] = wk2;
    wp.in[2] = Wv; wp.out[2] = wv2;
    wp.in[3] = W0; wp.out[3] = w02;
    split_multi<<<dim3(NW / 256, 4), 256>>>(wp, NW, 0);

    // fused q/k/v projections -> pre-split bf16 hi/lo planes
    GemmArgs pa;
    pa.A[0] = q2;  pa.A[1] = k2;  pa.A[2] = v2;
    pa.B[0] = wq2; pa.B[1] = wk2; pa.B[2] = wv2;
    pa.bias[0] = bq; pa.bias[1] = bk; pa.bias[2] = bv;
    pa.C[0] = pa.C[1] = pa.C[2] = nullptr;
    pa.Ch[0] = Qh; pa.Ch[1] = Kh; pa.Ch[2] = Vh;
    pa.Cl[0] = Ql; pa.Cl[1] = Kl; pa.Cl[2] = Vl;
    pa.mode = 1;
    gemm_mma<<<dim3(DMOD / 128, M / 128, 3), 256>>>(pa, DMOD);

    // tensor-core fused attention v4
    cudaFuncSetAttribute(attn_mma,
                         cudaFuncAttributeMaxDynamicSharedMemorySize, ATT_SMEM);
    attn_mma<<<dim3(SS / 128, HH, BB), 256, ATT_SMEM>>>(
        Qh, Ql, Kh, Kl, Vh, Vl, rkt, rvt, x2);

    // output projection (fp32 out)
    GemmArgs oa;
    oa.A[0] = x2;  oa.A[1] = x2;  oa.A[2] = x2;
    oa.B[0] = w02; oa.B[1] = w02; oa.B[2] = w02;
    oa.bias[0] = b0; oa.bias[1] = b0; oa.bias[2] = b0;
    oa.C[0] = (float*)d_out; oa.C[1] = (float*)d_out; oa.C[2] = (float*)d_out;
    oa.Ch[0] = oa.Ch[1] = oa.Ch[2] = nullptr;
    oa.Cl[0] = oa.Cl[1] = oa.Cl[2] = nullptr;
    oa.mode = 0;
    gemm_mma<<<dim3(DMOD / 128, M / 128, 1), 256>>>(oa, DMOD);
}

// round 13
// speedup vs baseline: 1.9680x; 1.0195x over previous
#include <cuda_runtime.h>
#include <cuda_bf16.h>
#include <cstdint>

#define BB 2
#define SS 1024
#define DMOD 1024
#define HH 16
#define DH 64
#define NR 21     // 2*MAX_REL+1
#define K3 3072   // 3 * DMOD (split-concatenated K)

// ============================================================================
// scratch (static device globals: no allocations allowed)
// ============================================================================
__device__ __nv_bfloat16 g_Qh[BB * SS * DMOD];
__device__ __nv_bfloat16 g_Ql[BB * SS * DMOD];
__device__ __nv_bfloat16 g_Kh[BB * SS * DMOD];
__device__ __nv_bfloat16 g_Kl[BB * SS * DMOD];
__device__ __nv_bfloat16 g_Vh[BB * SS * DMOD];
__device__ __nv_bfloat16 g_Vl[BB * SS * DMOD];

__device__ __nv_bfloat16 g_q2[BB * SS * K3];
__device__ __nv_bfloat16 g_k2[BB * SS * K3];
__device__ __nv_bfloat16 g_v2[BB * SS * K3];
__device__ __nv_bfloat16 g_x2[BB * SS * K3];
__device__ __nv_bfloat16 g_wq2[DMOD * K3];
__device__ __nv_bfloat16 g_wk2[DMOD * K3];
__device__ __nv_bfloat16 g_wv2[DMOD * K3];
__device__ __nv_bfloat16 g_w02[DMOD * K3];

// ============================================================================
// batched split kernel: fp32 -> bf16 hi/lo, written K-concatenated.
// ============================================================================
struct SplitPack {
    const float* in[4];
    __nv_bfloat16* out[4];
};

__global__ __launch_bounds__(256) void split_multi(SplitPack p, int n, int is_act) {
    int i = blockIdx.x * blockDim.x + threadIdx.x;
    if (i >= n) return;
    const float* in = p.in[blockIdx.y];
    __nv_bfloat16* out = p.out[blockIdx.y];
    int m = i >> 10;          // K = 1024
    int k = i & 1023;
    float x = in[i];
    __nv_bfloat16 h = __float2bfloat16_rn(x);
    float r = x - __bfloat162float(h);
    __nv_bfloat16 l = __float2bfloat16_rn(r);
    size_t base = (size_t)m * K3 + k;
    out[base] = h;
    if (is_act) {
        out[base + 1024] = l;
        out[base + 2048] = h;
    } else {
        out[base + 1024] = h;
        out[base + 2048] = l;
    }
}

// ============================================================================
// mma.sync / cp.async helpers
// ============================================================================
__device__ __forceinline__ uint32_t smem_u32(const void* p) {
    uint32_t a;
    asm("{ .reg .u64 t; cvta.to.shared.u64 t, %1; cvt.u32.u64 %0, t; }"
        : "=r"(a) : "l"(p));
    return a;
}

#define CP_ASYNC16(dst, src) \
    asm volatile("cp.async.cg.shared.global [%0], [%1], 16;" \
                 :: "r"(dst), "l"(src) : "memory")
#define CP_COMMIT() asm volatile("cp.async.commit_group;" ::: "memory")
#define CP_WAIT0()  asm volatile("cp.async.wait_group 0;" ::: "memory")

__device__ __forceinline__ void ldmx4(uint32_t& r0, uint32_t& r1,
                                      uint32_t& r2, uint32_t& r3,
                                      uint32_t addr) {
    asm volatile(
        "ldmatrix.sync.aligned.m8n8.x4.shared.b16 {%0,%1,%2,%3}, [%4];"
        : "=r"(r0), "=r"(r1), "=r"(r2), "=r"(r3) : "r"(addr));
}

__device__ __forceinline__ void ldmx4t(uint32_t& r0, uint32_t& r1,
                                       uint32_t& r2, uint32_t& r3,
                                       uint32_t addr) {
    asm volatile(
        "ldmatrix.sync.aligned.m8n8.x4.trans.shared.b16 {%0,%1,%2,%3}, [%4];"
        : "=r"(r0), "=r"(r1), "=r"(r2), "=r"(r3) : "r"(addr));
}

__device__ __forceinline__ void mma16816(float* c, const uint32_t* a,
                                         const uint32_t* b) {
    asm volatile(
        "mma.sync.aligned.m16n8k16.row.col.f32.bf16.bf16.f32 "
        "{%0,%1,%2,%3}, {%4,%5,%6,%7}, {%8,%9}, {%0,%1,%2,%3};"
        : "+f"(c[0]), "+f"(c[1]), "+f"(c[2]), "+f"(c[3])
        : "r"(a[0]), "r"(a[1]), "r"(a[2]), "r"(a[3]), "r"(b[0]), "r"(b[1]));
}

__device__ __forceinline__ void split2(float x, __nv_bfloat16& h, __nv_bfloat16& l) {
    h = __float2bfloat16_rn(x);
    l = __float2bfloat16_rn(x - __bfloat162float(h));
}

__device__ __forceinline__ uint32_t pack_bf2(__nv_bfloat16 a, __nv_bfloat16 b) {
    __nv_bfloat162 p = __halves2bfloat162(a, b);
    return *(uint32_t*)&p;
}

// ============================================================================
// bf16 HMMA GEMM over K3, cp.async single-sync pipeline, 2 CTAs/SM.
// mode 0: C fp32 = acc + bias;  mode 1: split bf16 hi/lo planes.
// ============================================================================
struct GemmArgs {
    const __nv_bfloat16* A[3];
    const __nv_bfloat16* B[3];
    const float* bias[3];
    float* C[3];
    __nv_bfloat16* Ch[3];
    __nv_bfloat16* Cl[3];
    int mode;
};

#define BK 32
#define RS 40
#define BUFH (128 * RS)

__global__ __launch_bounds__(256, 2) void gemm_mma(GemmArgs ga, int N) {
    __shared__ __align__(16) __nv_bfloat16 As[2][BUFH];
    __shared__ __align__(16) __nv_bfloat16 Bs[2][BUFH];

    const int t = threadIdx.x;
    const int lane = t & 31;
    const int wid = t >> 5;
    const int wm = (wid & 1) * 64;
    const int wn = (wid >> 1) * 32;
    const int grp = lane >> 2;
    const int tig = lane & 3;
    const int z = blockIdx.z;
    const int m0 = blockIdx.y * 128;
    const int n0 = blockIdx.x * 128;

    const __nv_bfloat16* Ag = ga.A[z];
    const __nv_bfloat16* Bg = ga.B[z];
    const float* bias = ga.bias[z];

    const int lrow = t >> 1;
    const int lcol = (t & 1) * 16;
    const __nv_bfloat16* Ap = Ag + (size_t)(m0 + lrow) * K3 + lcol;
    const __nv_bfloat16* Bp = Bg + (size_t)(n0 + lrow) * K3 + lcol;
    const uint32_t sst = lrow * (RS * 2) + lcol * 2;

    const uint32_t asb = smem_u32(As);
    const uint32_t bsb = smem_u32(Bs);

    const uint32_t a_base = asb + (wm + (lane & 15)) * (RS * 2) + ((lane >> 4) * 8) * 2;
    const uint32_t b_base = bsb + (wn + (lane & 7) + ((lane >> 4) & 1) * 8) * (RS * 2) +
                            (((lane >> 3) & 1) * 8) * 2;

    float acc[4][4][4];
#pragma unroll
    for (int mi = 0; mi < 4; ++mi)
#pragma unroll
        for (int ni = 0; ni < 4; ++ni)
#pragma unroll
            for (int r = 0; r < 4; ++r) acc[mi][ni][r] = 0.f;

    // prologue: async-load tile 0 into buf 0
    CP_ASYNC16(asb + sst,      Ap);
    CP_ASYNC16(asb + sst + 16, Ap + 8);
    CP_ASYNC16(bsb + sst,      Bp);
    CP_ASYNC16(bsb + sst + 16, Bp + 8);
    CP_COMMIT();

    const int NT = K3 / BK;
    for (int kt = 0; kt < NT; ++kt) {
        const int buf = kt & 1;
        CP_WAIT0();          // only pending group = this iter's tile
        __syncthreads();     // all threads see it; prev buf^1 reads all done

        if (kt + 1 < NT) {
            const uint32_t nb = (buf ^ 1) * (BUFH * 2);
            const __nv_bfloat16* an = Ap + (size_t)(kt + 1) * BK;
            const __nv_bfloat16* bn = Bp + (size_t)(kt + 1) * BK;
            CP_ASYNC16(asb + nb + sst,      an);
            CP_ASYNC16(asb + nb + sst + 16, an + 8);
            CP_ASYNC16(bsb + nb + sst,      bn);
            CP_ASYNC16(bsb + nb + sst + 16, bn + 8);
            CP_COMMIT();
        }

        const uint32_t abuf = a_base + buf * (BUFH * 2);
        const uint32_t bbuf = b_base + buf * (BUFH * 2);
#pragma unroll
        for (int ks = 0; ks < 2; ++ks) {
            uint32_t a[4][4], b[4][2];
#pragma unroll
            for (int mi = 0; mi < 4; ++mi)
                ldmx4(a[mi][0], a[mi][1], a[mi][2], a[mi][3],
                      abuf + mi * 16 * (RS * 2) + ks * 32);
#pragma unroll
            for (int nb2 = 0; nb2 < 2; ++nb2)
                ldmx4(b[nb2 * 2][0], b[nb2 * 2][1], b[nb2 * 2 + 1][0],
                      b[nb2 * 2 + 1][1],
                      bbuf + nb2 * 16 * (RS * 2) + ks * 32);
#pragma unroll
            for (int mi = 0; mi < 4; ++mi)
#pragma unroll
                for (int ni = 0; ni < 4; ++ni)
                    mma16816(acc[mi][ni], a[mi], b[ni]);
        }
    }

    if (ga.mode == 0) {
        float* C = ga.C[z];
#pragma unroll
        for (int ni = 0; ni < 4; ++ni) {
            const int col = n0 + wn + ni * 8 + tig * 2;
            const float2 bv = *(const float2*)&bias[col];
#pragma unroll
            for (int mi = 0; mi < 4; ++mi) {
                const int row = m0 + wm + mi * 16 + grp;
                *(float2*)&C[(size_t)row * N + col] =
                    make_float2(acc[mi][ni][0] + bv.x, acc[mi][ni][1] + bv.y);
                *(float2*)&C[(size_t)(row + 8) * N + col] =
                    make_float2(acc[mi][ni][2] + bv.x, acc[mi][ni][3] + bv.y);
            }
        }
    } else {
        __nv_bfloat16* Ch = ga.Ch[z];
        __nv_bfloat16* Cl = ga.Cl[z];
#pragma unroll
        for (int ni = 0; ni < 4; ++ni) {
            const int col = n0 + wn + ni * 8 + tig * 2;
            const float2 bv = *(const float2*)&bias[col];
#pragma unroll
            for (int mi = 0; mi < 4; ++mi) {
                const int row = m0 + wm + mi * 16 + grp;
                float f00 = acc[mi][ni][0] + bv.x, f01 = acc[mi][ni][1] + bv.y;
                float f10 = acc[mi][ni][2] + bv.x, f11 = acc[mi][ni][3] + bv.y;
                __nv_bfloat16 h00, l00, h01, l01, h10, l10, h11, l11;
                split2(f00, h00, l00);
                split2(f01, h01, l01);
                split2(f10, h10, l10);
                split2(f11, h11, l11);
                const size_t i0 = (size_t)row * N + col;
                const size_t i1 = (size_t)(row + 8) * N + col;
                *(__nv_bfloat162*)(Ch + i0) = __halves2bfloat162(h00, h01);
                *(__nv_bfloat162*)(Cl + i0) = __halves2bfloat162(l00, l01);
                *(__nv_bfloat162*)(Ch + i1) = __halves2bfloat162(h10, h11);
                *(__nv_bfloat162*)(Cl + i1) = __halves2bfloat162(l10, l11);
            }
        }
    }
}

// ============================================================================
// Tensor-core fused attention v5 (FA2 register-S + clip-band fast path).
// 128-q-tile x 64-k-tile, 256 threads (8 warps), 2 CTAs/SM, single wave.
// ============================================================================
#define QRS 72           // halves per row; 144B (conflict-free for ldmatrix)
#define ATT_SMEM 105984
#define S32 0.03125f

__global__ __launch_bounds__(256, 2) void attn_mma(
    const __nv_bfloat16* __restrict__ Qhg, const __nv_bfloat16* __restrict__ Qlg,
    const __nv_bfloat16* __restrict__ Khg, const __nv_bfloat16* __restrict__ Klg,
    const __nv_bfloat16* __restrict__ Vhg, const __nv_bfloat16* __restrict__ Vlg,
    const float* __restrict__ rkt, const float* __restrict__ rvt,
    __nv_bfloat16* __restrict__ x2) {
    extern __shared__ char smc[];
    __nv_bfloat16* Qh = (__nv_bfloat16*)(smc);
    __nv_bfloat16* Ql = (__nv_bfloat16*)(smc + 18432);
    __nv_bfloat16* Kh = (__nv_bfloat16*)(smc + 36864);
    __nv_bfloat16* Kl = (__nv_bfloat16*)(smc + 46080);
    __nv_bfloat16* Vh = (__nv_bfloat16*)(smc + 55296);
    __nv_bfloat16* Vl = (__nv_bfloat16*)(smc + 64512);
    float* rk = (float*)(smc + 73728);
    float* rv = (float*)(smc + 79104);
    float* pp = (float*)(smc + 84480);
    float* cs = (float*)(smc + 95232);

    const uint32_t sQh = smem_u32(Qh), sQl = smem_u32(Ql);
    const uint32_t sKh = smem_u32(Kh), sKl = smem_u32(Kl);
    const uint32_t sVh = smem_u32(Vh), sVl = smem_u32(Vl);

    const int t = threadIdx.x;
    const int lane = t & 31;
    const int w = t >> 5;
    const int grp = lane >> 2;
    const int tig = lane & 3;
    const int q0 = blockIdx.x * 128;
    const int h = blockIdx.y;
    const int b = blockIdx.z;
    const size_t hoff = (size_t)h * DH;
    const size_t gbase = (size_t)b * SS * DMOD + hoff;

    const int ch = t & 7;
    const int r32 = t >> 3;

    {
        const __nv_bfloat16* qg[2] = {Qhg + gbase, Qlg + gbase};
        __nv_bfloat16* qs[2] = {Qh, Ql};
#pragma unroll
        for (int i = 0; i < 8; ++i) {
            const int pl = i >> 2;
            const int row = r32 + (i & 3) * 32;
            *(uint4*)(qs[pl] + row * QRS + ch * 8) =
                *(const uint4*)(qg[pl] + (size_t)(q0 + row) * DMOD + ch * 8);
        }
    }
    for (int i = t; i < NR * 64; i += 256) { rk[i] = rkt[i]; rv[i] = rvt[i]; }
    for (int i = t; i < 128 * NR; i += 256) cs[i] = 0.f;
    __syncthreads();

    for (int e = t; e < 128 * NR; e += 256) {
        int qq = e / NR, j = e - qq * NR;
        float s = 0.f;
#pragma unroll 16
        for (int d = 0; d < 64; ++d)
            s += (__bfloat162float(Qh[qq * QRS + d]) +
                  __bfloat162float(Ql[qq * QRS + d])) * rk[j * 64 + d];
        pp[e] = s;
    }

    float o[8][4];
#pragma unroll
    for (int ni = 0; ni < 8; ++ni)
#pragma unroll
        for (int r = 0; r < 4; ++r) o[ni][r] = 0.f;

    float l0a[2] = {0.f, 0.f};
    float l20a[2] = {0.f, 0.f};

    const uint32_t a_off = (w * 16 + (lane & 15)) * (QRS * 2) + ((lane >> 4) * 8) * 2;
    const uint32_t b_off = ((lane & 7) + ((lane >> 4) & 1) * 8) * (QRS * 2) +
                           (((lane >> 3) & 1) * 8) * 2;
    const uint32_t vb_row = (lane & 7) + ((lane >> 3) & 1) * 8;
    const uint32_t vb_cb  = ((lane >> 4) * 8) * 2;

    const __nv_bfloat16* kvg[4] = {Khg + gbase, Klg + gbase, Vhg + gbase, Vlg + gbase};
    __nv_bfloat16* kvs[4] = {Kh, Kl, Vh, Vl};

    for (int kt = 0; kt < 16; ++kt) {
        const int k0 = kt * 64;
        __syncthreads();

#pragma unroll
        for (int i = 0; i < 8; ++i) {
            const int pl = i >> 1;
            const int row = r32 + (i & 1) * 32;
            *(uint4*)(kvs[pl] + row * QRS + ch * 8) =
                *(const uint4*)(kvg[pl] + (size_t)(k0 + row) * DMOD + ch * 8);
        }
        __syncthreads();

        float s[8][4];
#pragma unroll
        for (int ni = 0; ni < 8; ++ni)
#pragma unroll
            for (int r = 0; r < 4; ++r) s[ni][r] = 0.f;

#pragma unroll
        for (int ks = 0; ks < 4; ++ks) {
            uint32_t ah[4], al[4];
            ldmx4(ah[0], ah[1], ah[2], ah[3], sQh + a_off + ks * 32);
            ldmx4(al[0], al[1], al[2], al[3], sQl + a_off + ks * 32);
#pragma unroll
            for (int nb = 0; nb < 4; ++nb) {
                uint32_t kh[4], kl[4];
                ldmx4(kh[0], kh[1], kh[2], kh[3],
                      sKh + b_off + nb * 16 * (QRS * 2) + ks * 32);
                ldmx4(kl[0], kl[1], kl[2], kl[3],
                      sKl + b_off + nb * 16 * (QRS * 2) + ks * 32);
                uint32_t bh0[2] = {kh[0], kh[1]}, bh1[2] = {kh[2], kh[3]};
                uint32_t bl0[2] = {kl[0], kl[1]}, bl1[2] = {kl[2], kl[3]};
                mma16816(s[nb * 2],     ah, bh0);
                mma16816(s[nb * 2],     al, bh0);
                mma16816(s[nb * 2],     ah, bl0);
                mma16816(s[nb * 2 + 1], ah, bh1);
                mma16816(s[nb * 2 + 1], al, bh1);
                mma16816(s[nb * 2 + 1], ah, bl1);
            }
        }

        // ---- postprocess: clip-band fast path (~14/16 tiles) or general ----
        uint32_t ahf[4][4], alf[4][4];
        const int wq0 = q0 + w * 16;
        const int dmax = k0 + 63 - wq0;        // largest d in warp tile
        const int dmin = k0 - (wq0 + 15);      // smallest d in warp tile

        if (dmax <= -10 || dmin >= 10) {
            // whole warp tile in one clip class: uniform pp, no per-elem logic
            const int cls = (dmax <= -10) ? 0 : 20;
            float* lacc = (dmax <= -10) ? l0a : l20a;
#pragma unroll
            for (int hf = 0; hf < 2; ++hf) {
                const int row = w * 16 + grp + hf * 8;
                const float ppc = pp[row * NR + cls];
                float acc = 0.f;
#pragma unroll
                for (int ni = 0; ni < 8; ++ni) {
                    const float f0 = (s[ni][hf * 2 + 0] + ppc) * S32;
                    const float f1 = (s[ni][hf * 2 + 1] + ppc) * S32;
                    acc += f0;
                    acc += f1;
                    __nv_bfloat16 h0, lo0, h1, lo1;
                    split2(f0, h0, lo0);
                    split2(f1, h1, lo1);
                    const int kc = ni >> 1;
                    const int sub = (ni & 1) * 2 + hf;
                    ahf[kc][sub] = pack_bf2(h0, h1);
                    alf[kc][sub] = pack_bf2(lo0, lo1);
                }
                lacc[hf] += acc;
            }
        } else {
#pragma unroll
            for (int ni = 0; ni < 8; ++ni) {
                const int colg = k0 + ni * 8 + tig * 2;
#pragma unroll
                for (int hf = 0; hf < 2; ++hf) {
                    const int row = w * 16 + grp + hf * 8;
                    const int gq = q0 + row;
                    const float* ppr = pp + row * NR;
                    const int d0 = colg - gq;
                    const int d1 = d0 + 1;
                    const int c0 = d0 < -10 ? 0 : (d0 > 10 ? 20 : d0 + 10);
                    const int c1 = d1 < -10 ? 0 : (d1 > 10 ? 20 : d1 + 10);
                    const float f0 = (s[ni][hf * 2 + 0] + ppr[c0]) * S32;
                    const float f1 = (s[ni][hf * 2 + 1] + ppr[c1]) * S32;
                    if (d0 <= -10)      l0a[hf]  += f0;
                    else if (d0 >= 10)  l20a[hf] += f0;
                    else                cs[row * NR + d0 + 10] += f0;
                    if (d1 <= -10)      l0a[hf]  += f1;
                    else if (d1 >= 10)  l20a[hf] += f1;
                    else                cs[row * NR + d1 + 10] += f1;
                    __nv_bfloat16 h0, lo0, h1, lo1;
                    split2(f0, h0, lo0);
                    split2(f1, h1, lo1);
                    const int kc = ni >> 1;
                    const int sub = (ni & 1) * 2 + hf;
                    ahf[kc][sub] = pack_bf2(h0, h1);
                    alf[kc][sub] = pack_bf2(lo0, lo1);
                }
            }
        }

#pragma unroll
        for (int kc = 0; kc < 4; ++kc) {
#pragma unroll
            for (int nb = 0; nb < 4; ++nb) {
                uint32_t vh[4], vl[4];
                ldmx4t(vh[0], vh[1], vh[2], vh[3],
                       sVh + (kc * 16 + vb_row) * (QRS * 2) + vb_cb + nb * 32);
                ldmx4t(vl[0], vl[1], vl[2], vl[3],
                       sVl + (kc * 16 + vb_row) * (QRS * 2) + vb_cb + nb * 32);
                uint32_t bh0[2] = {vh[0], vh[1]}, bh1[2] = {vh[2], vh[3]};
                uint32_t bl0[2] = {vl[0], vl[1]}, bl1[2] = {vl[2], vl[3]};
                mma16816(o[nb * 2],     ahf[kc], bh0);
                mma16816(o[nb * 2],     alf[kc], bh0);
                mma16816(o[nb * 2],     ahf[kc], bl0);
                mma16816(o[nb * 2 + 1], ahf[kc], bh1);
                mma16816(o[nb * 2 + 1], alf[kc], bh1);
                mma16816(o[nb * 2 + 1], ahf[kc], bl1);
            }
        }
    }

#pragma unroll
    for (int hf = 0; hf < 2; ++hf) {
        float v0 = l0a[hf];
        v0 += __shfl_xor_sync(0xffffffffu, v0, 1);
        v0 += __shfl_xor_sync(0xffffffffu, v0, 2);
        float v20 = l20a[hf];
        v20 += __shfl_xor_sync(0xffffffffu, v20, 1);
        v20 += __shfl_xor_sync(0xffffffffu, v20, 2);
        if (tig == 0) {
            const int row = w * 16 + grp + hf * 8;
            cs[row * NR + 0]  += v0;
            cs[row * NR + 20] += v20;
        }
    }
    __syncwarp();

#pragma unroll
    for (int ni = 0; ni < 8; ++ni) {
#pragma unroll
        for (int hf = 0; hf < 2; ++hf) {
            const int row = w * 16 + grp + hf * 8;
            const int col = ni * 8 + tig * 2;
            float a0 = o[ni][hf * 2 + 0];
            float a1 = o[ni][hf * 2 + 1];
            const float* csr = cs + row * NR;
#pragma unroll
            for (int j = 0; j < NR; ++j) {
                const float c = csr[j];
                a0 += c * rv[j * 64 + col];
                a1 += c * rv[j * 64 + col + 1];
            }
            __nv_bfloat16 h0, l0b, h1, l1b;
            split2(a0, h0, l0b);
            split2(a1, h1, l1b);
            const size_t base = ((size_t)b * SS + q0 + row) * K3 + hoff + col;
            const __nv_bfloat162 hi2 = __halves2bfloat162(h0, h1);
            *(__nv_bfloat162*)(x2 + base)        = hi2;
            *(__nv_bfloat162*)(x2 + base + 1024) = __halves2bfloat162(l0b, l1b);
            *(__nv_bfloat162*)(x2 + base + 2048) = hi2;
        }
    }
}

// ============================================================================
// launch
// ============================================================================
extern "C" void kernel_launch(void* const* d_in, const int* in_sizes, int n_in,
                              void* d_out, int out_size) {
    const float* q   = (const float*)d_in[0];
    const float* k   = (const float*)d_in[1];
    const float* v   = (const float*)d_in[2];
    const float* Wq  = (const float*)d_in[4];
    const float* bq  = (const float*)d_in[5];
    const float* Wk  = (const float*)d_in[6];
    const float* bk  = (const float*)d_in[7];
    const float* Wv  = (const float*)d_in[8];
    const float* bv  = (const float*)d_in[9];
    const float* W0  = (const float*)d_in[10];
    const float* b0  = (const float*)d_in[11];
    const float* rkt = (const float*)d_in[12];
    const float* rvt = (const float*)d_in[13];

    __nv_bfloat16 *Qh, *Ql, *Kh, *Kl, *Vh, *Vl;
    cudaGetSymbolAddress((void**)&Qh, g_Qh);
    cudaGetSymbolAddress((void**)&Ql, g_Ql);
    cudaGetSymbolAddress((void**)&Kh, g_Kh);
    cudaGetSymbolAddress((void**)&Kl, g_Kl);
    cudaGetSymbolAddress((void**)&Vh, g_Vh);
    cudaGetSymbolAddress((void**)&Vl, g_Vl);
    __nv_bfloat16 *q2, *k2, *v2, *x2, *wq2, *wk2, *wv2, *w02;
    cudaGetSymbolAddress((void**)&q2, g_q2);
    cudaGetSymbolAddress((void**)&k2, g_k2);
    cudaGetSymbolAddress((void**)&v2, g_v2);
    cudaGetSymbolAddress((void**)&x2, g_x2);
    cudaGetSymbolAddress((void**)&wq2, g_wq2);
    cudaGetSymbolAddress((void**)&wk2, g_wk2);
    cudaGetSymbolAddress((void**)&wv2, g_wv2);
    cudaGetSymbolAddress((void**)&w02, g_w02);

    const int M = BB * SS;          // 2048
    const int NACT = M * DMOD;
    const int NW = DMOD * DMOD;

    SplitPack ap;
    ap.in[0] = q;  ap.out[0] = q2;
    ap.in[1] = k;  ap.out[1] = k2;
    ap.in[2] = v;  ap.out[2] = v2;
    ap.in[3] = q;  ap.out[3] = q2;   // unused
    split_multi<<<dim3(NACT / 256, 3), 256>>>(ap, NACT, 1);
    SplitPack wp;
    wp.in[0] = Wq; wp.out[0] = wq2;
    wp.in[1] = Wk; wp.out[1] = wk2;
    wp.in[2] = Wv; wp.out[2] = wv2;
    wp.in[3] = W0; wp.out[3] = w02;
    split_multi<<<dim3(NW / 256, 4), 256>>>(wp, NW, 0);

    // fused q/k/v projections -> pre-split bf16 hi/lo planes
    GemmArgs pa;
    pa.A[0] = q2;  pa.A[1] = k2;  pa.A[2] = v2;
    pa.B[0] = wq2; pa.B[1] = wk2; pa.B[2] = wv2;
    pa.bias[0] = bq; pa.bias[1] = bk; pa.bias[2] = bv;
    pa.C[0] = pa.C[1] = pa.C[2] = nullptr;
    pa.Ch[0] = Qh; pa.Ch[1] = Kh; pa.Ch[2] = Vh;
    pa.Cl[0] = Ql; pa.Cl[1] = Kl; pa.Cl[2] = Vl;
    pa.mode = 1;
    gemm_mma<<<dim3(DMOD / 128, M / 128, 3), 256>>>(pa, DMOD);

    // tensor-core fused attention v5
    cudaFuncSetAttribute(attn_mma,
                         cudaFuncAttributeMaxDynamicSharedMemorySize, ATT_SMEM);
    attn_mma<<<dim3(SS / 128, HH, BB), 256, ATT_SMEM>>>(
        Qh, Ql, Kh, Kl, Vh, Vl, rkt, rvt, x2);

    // output projection (fp32 out)
    GemmArgs oa;
    oa.A[0] = x2;  oa.A[1] = x2;  oa.A[2] = x2;
    oa.B[0] = w02; oa.B[1] = w02; oa.B[2] = w02;
    oa.bias[0] = b0; oa.bias[1] = b0; oa.bias[2] = b0;
    oa.C[0] = (float*)d_out; oa.C[1] = (float*)d_out; oa.C[2] = (float*)d_out;
    oa.Ch[0] = oa.Ch[1] = oa.Ch[2] = nullptr;
    oa.Cl[0] = oa.Cl[1] = oa.Cl[2] = nullptr;
    oa.mode = 0;
    gemm_mma<<<dim3(DMOD / 128, M / 128, 1), 256>>>(oa, DMOD);
}

// round 14
// speedup vs baseline: 2.1122x; 1.0733x over previous
#include <cuda_runtime.h>
#include <cuda_bf16.h>
#include <cstdint>

#define BB 2
#define SS 1024
#define DMOD 1024
#define HH 16
#define DH 64
#define NR 21     // 2*MAX_REL+1
#define K2 2048   // 2-plane storage: [hi | lo] per row
// logical GEMM K = 3072 via region remap: A:(hi,lo,hi)  B:(hi,hi,lo)

// ============================================================================
// scratch (static device globals: no allocations allowed)
// ============================================================================
__device__ __nv_bfloat16 g_Qh[BB * SS * DMOD];
__device__ __nv_bfloat16 g_Ql[BB * SS * DMOD];
__device__ __nv_bfloat16 g_Kh[BB * SS * DMOD];
__device__ __nv_bfloat16 g_Kl[BB * SS * DMOD];
__device__ __nv_bfloat16 g_Vh[BB * SS * DMOD];
__device__ __nv_bfloat16 g_Vl[BB * SS * DMOD];

__device__ __nv_bfloat16 g_q2[BB * SS * K2];
__device__ __nv_bfloat16 g_k2[BB * SS * K2];
__device__ __nv_bfloat16 g_v2[BB * SS * K2];
__device__ __nv_bfloat16 g_x2[BB * SS * K2];
__device__ __nv_bfloat16 g_wq2[DMOD * K2];
__device__ __nv_bfloat16 g_wk2[DMOD * K2];
__device__ __nv_bfloat16 g_wv2[DMOD * K2];
__device__ __nv_bfloat16 g_w02[DMOD * K2];

// ============================================================================
// batched split kernel: fp32 -> bf16 [hi | lo] (one flavor, 7 tensors, 1 launch)
// ============================================================================
struct SplitPack {
    const float* in[7];
    __nv_bfloat16* out[7];
    int n[7];
};

__global__ __launch_bounds__(256) void split_multi(SplitPack p) {
    const int sl = blockIdx.y;
    const int n = p.n[sl];
    int i = blockIdx.x * blockDim.x + threadIdx.x;
    if (i >= n) return;
    const float* in = p.in[sl];
    __nv_bfloat16* out = p.out[sl];
    int m = i >> 10;          // K = 1024
    int k = i & 1023;
    float x = in[i];
    __nv_bfloat16 h = __float2bfloat16_rn(x);
    float r = x - __bfloat162float(h);
    __nv_bfloat16 l = __float2bfloat16_rn(r);
    size_t base = (size_t)m * K2 + k;
    out[base] = h;
    out[base + 1024] = l;
}

// ============================================================================
// mma.sync / cp.async helpers
// ============================================================================
__device__ __forceinline__ uint32_t smem_u32(const void* p) {
    uint32_t a;
    asm("{ .reg .u64 t; cvta.to.shared.u64 t, %1; cvt.u32.u64 %0, t; }"
        : "=r"(a) : "l"(p));
    return a;
}

#define CP_ASYNC16(dst, src) \
    asm volatile("cp.async.cg.shared.global [%0], [%1], 16;" \
                 :: "r"(dst), "l"(src) : "memory")
#define CP_COMMIT() asm volatile("cp.async.commit_group;" ::: "memory")
#define CP_WAIT0()  asm volatile("cp.async.wait_group 0;" ::: "memory")

__device__ __forceinline__ void ldmx4(uint32_t& r0, uint32_t& r1,
                                      uint32_t& r2, uint32_t& r3,
                                      uint32_t addr) {
    asm volatile(
        "ldmatrix.sync.aligned.m8n8.x4.shared.b16 {%0,%1,%2,%3}, [%4];"
        : "=r"(r0), "=r"(r1), "=r"(r2), "=r"(r3) : "r"(addr));
}

__device__ __forceinline__ void ldmx4t(uint32_t& r0, uint32_t& r1,
                                       uint32_t& r2, uint32_t& r3,
                                       uint32_t addr) {
    asm volatile(
        "ldmatrix.sync.aligned.m8n8.x4.trans.shared.b16 {%0,%1,%2,%3}, [%4];"
        : "=r"(r0), "=r"(r1), "=r"(r2), "=r"(r3) : "r"(addr));
}

__device__ __forceinline__ void mma16816(float* c, const uint32_t* a,
                                         const uint32_t* b) {
    asm volatile(
        "mma.sync.aligned.m16n8k16.row.col.f32.bf16.bf16.f32 "
        "{%0,%1,%2,%3}, {%4,%5,%6,%7}, {%8,%9}, {%0,%1,%2,%3};"
        : "+f"(c[0]), "+f"(c[1]), "+f"(c[2]), "+f"(c[3])
        : "r"(a[0]), "r"(a[1]), "r"(a[2]), "r"(a[3]), "r"(b[0]), "r"(b[1]));
}

__device__ __forceinline__ void split2(float x, __nv_bfloat16& h, __nv_bfloat16& l) {
    h = __float2bfloat16_rn(x);
    l = __float2bfloat16_rn(x - __bfloat162float(h));
}

__device__ __forceinline__ uint32_t pack_bf2(__nv_bfloat16 a, __nv_bfloat16 b) {
    __nv_bfloat162 p = __halves2bfloat162(a, b);
    return *(uint32_t*)&p;
}

// ============================================================================
// bf16 HMMA GEMM, logical K=3072 over 2-plane storage, BK=64,
// cp.async single-sync pipeline, 2 CTAs/SM, dynamic smem 73728 B.
// mode 0: C fp32 = acc + bias;  mode 1: split bf16 hi/lo planes.
// ============================================================================
struct GemmArgs {
    const __nv_bfloat16* A[3];
    const __nv_bfloat16* B[3];
    const float* bias[3];
    float* C[3];
    __nv_bfloat16* Ch[3];
    __nv_bfloat16* Cl[3];
    int mode;
};

#define GRS 72                    // halves per smem row (144 B)
#define GBUF (128 * GRS)          // halves per stage buffer
#define GSMEM (4 * GBUF * 2)      // 73728 B (A0,A1,B0,B1)

__global__ __launch_bounds__(256, 2) void gemm_mma(GemmArgs ga, int N) {
    extern __shared__ __align__(16) __nv_bfloat16 gsm[];
    __nv_bfloat16* As = gsm;                 // [2][GBUF]
    __nv_bfloat16* Bs = gsm + 2 * GBUF;      // [2][GBUF]

    const int t = threadIdx.x;
    const int lane = t & 31;
    const int wid = t >> 5;
    const int wm = (wid & 1) * 64;
    const int wn = (wid >> 1) * 32;
    const int grp = lane >> 2;
    const int tig = lane & 3;
    const int z = blockIdx.z;
    const int m0 = blockIdx.y * 128;
    const int n0 = blockIdx.x * 128;

    const __nv_bfloat16* Ag = ga.A[z];
    const __nv_bfloat16* Bg = ga.B[z];
    const float* bias = ga.bias[z];

    // loader mapping: thread t -> row t>>1, 32-half (64B) chunk (t&1)
    const int lrow = t >> 1;
    const int lcol = (t & 1) * 32;           // halves within BK=64
    const __nv_bfloat16* Ap = Ag + (size_t)(m0 + lrow) * K2;
    const __nv_bfloat16* Bp = Bg + (size_t)(n0 + lrow) * K2;
    const uint32_t sst = lrow * (GRS * 2) + lcol * 2;  // smem byte offset in stage

    const uint32_t asb = smem_u32(As);
    const uint32_t bsb = smem_u32(Bs);

    const uint32_t a_base = asb + (wm + (lane & 15)) * (GRS * 2) + ((lane >> 4) * 8) * 2;
    const uint32_t b_base = bsb + (wn + (lane & 7) + ((lane >> 4) & 1) * 8) * (GRS * 2) +
                            (((lane >> 3) & 1) * 8) * 2;

    float acc[4][4][4];
#pragma unroll
    for (int mi = 0; mi < 4; ++mi)
#pragma unroll
        for (int ni = 0; ni < 4; ++ni)
#pragma unroll
            for (int r = 0; r < 4; ++r) acc[mi][ni][r] = 0.f;

    // region remap (in halves within a K2 row):
    //   A (activations): regions hi, lo, hi   -> {0, 1024, 0}
    //   B (weights):     regions hi, hi, lo   -> {0, 0, 1024}
    auto a_src = [&](int kt) {
        const int reg = kt >> 4;
        const int ko = (kt & 15) * 64 + lcol;
        return Ap + (reg == 1 ? 1024 : 0) + ko;
    };
    auto b_src = [&](int kt) {
        const int reg = kt >> 4;
        const int ko = (kt & 15) * 64 + lcol;
        return Bp + (reg == 2 ? 1024 : 0) + ko;
    };

    // prologue: async-load tile 0 into stage 0
    {
        const __nv_bfloat16* a0 = a_src(0);
        const __nv_bfloat16* b0 = b_src(0);
#pragma unroll
        for (int c = 0; c < 4; ++c) {
            CP_ASYNC16(asb + sst + c * 16, a0 + c * 8);
            CP_ASYNC16(bsb + sst + c * 16, b0 + c * 8);
        }
        CP_COMMIT();
    }

    const int NT = 48;   // 3072 / 64
    for (int kt = 0; kt < NT; ++kt) {
        const int buf = kt & 1;
        CP_WAIT0();
        __syncthreads();

        if (kt + 1 < NT) {
            const uint32_t nb = (buf ^ 1) * (GBUF * 2);
            const __nv_bfloat16* an = a_src(kt + 1);
            const __nv_bfloat16* bn = b_src(kt + 1);
#pragma unroll
            for (int c = 0; c < 4; ++c) {
                CP_ASYNC16(asb + nb + sst + c * 16, an + c * 8);
                CP_ASYNC16(bsb + nb + sst + c * 16, bn + c * 8);
            }
            CP_COMMIT();
        }

        const uint32_t abuf = a_base + buf * (GBUF * 2);
        const uint32_t bbuf = b_base + buf * (GBUF * 2);
#pragma unroll
        for (int ks = 0; ks < 4; ++ks) {
            uint32_t a[4][4], b[4][2];
#pragma unroll
            for (int mi = 0; mi < 4; ++mi)
                ldmx4(a[mi][0], a[mi][1], a[mi][2], a[mi][3],
                      abuf + mi * 16 * (GRS * 2) + ks * 32);
#pragma unroll
            for (int nb2 = 0; nb2 < 2; ++nb2)
                ldmx4(b[nb2 * 2][0], b[nb2 * 2][1], b[nb2 * 2 + 1][0],
                      b[nb2 * 2 + 1][1],
                      bbuf + nb2 * 16 * (GRS * 2) + ks * 32);
#pragma unroll
            for (int mi = 0; mi < 4; ++mi)
#pragma unroll
                for (int ni = 0; ni < 4; ++ni)
                    mma16816(acc[mi][ni], a[mi], b[ni]);
        }
    }

    if (ga.mode == 0) {
        float* C = ga.C[z];
#pragma unroll
        for (int ni = 0; ni < 4; ++ni) {
            const int col = n0 + wn + ni * 8 + tig * 2;
            const float2 bv = *(const float2*)&bias[col];
#pragma unroll
            for (int mi = 0; mi < 4; ++mi) {
                const int row = m0 + wm + mi * 16 + grp;
                *(float2*)&C[(size_t)row * N + col] =
                    make_float2(acc[mi][ni][0] + bv.x, acc[mi][ni][1] + bv.y);
                *(float2*)&C[(size_t)(row + 8) * N + col] =
                    make_float2(acc[mi][ni][2] + bv.x, acc[mi][ni][3] + bv.y);
            }
        }
    } else {
        __nv_bfloat16* Ch = ga.Ch[z];
        __nv_bfloat16* Cl = ga.Cl[z];
#pragma unroll
        for (int ni = 0; ni < 4; ++ni) {
            const int col = n0 + wn + ni * 8 + tig * 2;
            const float2 bv = *(const float2*)&bias[col];
#pragma unroll
            for (int mi = 0; mi < 4; ++mi) {
                const int row = m0 + wm + mi * 16 + grp;
                float f00 = acc[mi][ni][0] + bv.x, f01 = acc[mi][ni][1] + bv.y;
                float f10 = acc[mi][ni][2] + bv.x, f11 = acc[mi][ni][3] + bv.y;
                __nv_bfloat16 h00, l00, h01, l01, h10, l10, h11, l11;
                split2(f00, h00, l00);
                split2(f01, h01, l01);
                split2(f10, h10, l10);
                split2(f11, h11, l11);
                const size_t i0 = (size_t)row * N + col;
                const size_t i1 = (size_t)(row + 8) * N + col;
                *(__nv_bfloat162*)(Ch + i0) = __halves2bfloat162(h00, h01);
                *(__nv_bfloat162*)(Cl + i0) = __halves2bfloat162(l00, l01);
                *(__nv_bfloat162*)(Ch + i1) = __halves2bfloat162(h10, h11);
                *(__nv_bfloat162*)(Cl + i1) = __halves2bfloat162(l10, l11);
            }
        }
    }
}

// ============================================================================
// Tensor-core fused attention v5 (FA2 register-S + clip-band fast path).
// Epilogue writes x2 in 2-plane [hi | lo] layout.
// ============================================================================
#define QRS 72
#define ATT_SMEM 105984
#define S32 0.03125f

__global__ __launch_bounds__(256, 2) void attn_mma(
    const __nv_bfloat16* __restrict__ Qhg, const __nv_bfloat16* __restrict__ Qlg,
    const __nv_bfloat16* __restrict__ Khg, const __nv_bfloat16* __restrict__ Klg,
    const __nv_bfloat16* __restrict__ Vhg, const __nv_bfloat16* __restrict__ Vlg,
    const float* __restrict__ rkt, const float* __restrict__ rvt,
    __nv_bfloat16* __restrict__ x2) {
    extern __shared__ char smc[];
    __nv_bfloat16* Qh = (__nv_bfloat16*)(smc);
    __nv_bfloat16* Ql = (__nv_bfloat16*)(smc + 18432);
    __nv_bfloat16* Kh = (__nv_bfloat16*)(smc + 36864);
    __nv_bfloat16* Kl = (__nv_bfloat16*)(smc + 46080);
    __nv_bfloat16* Vh = (__nv_bfloat16*)(smc + 55296);
    __nv_bfloat16* Vl = (__nv_bfloat16*)(smc + 64512);
    float* rk = (float*)(smc + 73728);
    float* rv = (float*)(smc + 79104);
    float* pp = (float*)(smc + 84480);
    float* cs = (float*)(smc + 95232);

    const uint32_t sQh = smem_u32(Qh), sQl = smem_u32(Ql);
    const uint32_t sKh = smem_u32(Kh), sKl = smem_u32(Kl);
    const uint32_t sVh = smem_u32(Vh), sVl = smem_u32(Vl);

    const int t = threadIdx.x;
    const int lane = t & 31;
    const int w = t >> 5;
    const int grp = lane >> 2;
    const int tig = lane & 3;
    const int q0 = blockIdx.x * 128;
    const int h = blockIdx.y;
    const int b = blockIdx.z;
    const size_t hoff = (size_t)h * DH;
    const size_t gbase = (size_t)b * SS * DMOD + hoff;

    const int ch = t & 7;
    const int r32 = t >> 3;

    {
        const __nv_bfloat16* qg[2] = {Qhg + gbase, Qlg + gbase};
        __nv_bfloat16* qs[2] = {Qh, Ql};
#pragma unroll
        for (int i = 0; i < 8; ++i) {
            const int pl = i >> 2;
            const int row = r32 + (i & 3) * 32;
            *(uint4*)(qs[pl] + row * QRS + ch * 8) =
                *(const uint4*)(qg[pl] + (size_t)(q0 + row) * DMOD + ch * 8);
        }
    }
    for (int i = t; i < NR * 64; i += 256) { rk[i] = rkt[i]; rv[i] = rvt[i]; }
    for (int i = t; i < 128 * NR; i += 256) cs[i] = 0.f;
    __syncthreads();

    for (int e = t; e < 128 * NR; e += 256) {
        int qq = e / NR, j = e - qq * NR;
        float s = 0.f;
#pragma unroll 16
        for (int d = 0; d < 64; ++d)
            s += (__bfloat162float(Qh[qq * QRS + d]) +
                  __bfloat162float(Ql[qq * QRS + d])) * rk[j * 64 + d];
        pp[e] = s;
    }

    float o[8][4];
#pragma unroll
    for (int ni = 0; ni < 8; ++ni)
#pragma unroll
        for (int r = 0; r < 4; ++r) o[ni][r] = 0.f;

    float l0a[2] = {0.f, 0.f};
    float l20a[2] = {0.f, 0.f};

    const uint32_t a_off = (w * 16 + (lane & 15)) * (QRS * 2) + ((lane >> 4) * 8) * 2;
    const uint32_t b_off = ((lane & 7) + ((lane >> 4) & 1) * 8) * (QRS * 2) +
                           (((lane >> 3) & 1) * 8) * 2;
    const uint32_t vb_row = (lane & 7) + ((lane >> 3) & 1) * 8;
    const uint32_t vb_cb  = ((lane >> 4) * 8) * 2;

    const __nv_bfloat16* kvg[4] = {Khg + gbase, Klg + gbase, Vhg + gbase, Vlg + gbase};
    __nv_bfloat16* kvs[4] = {Kh, Kl, Vh, Vl};

    for (int kt = 0; kt < 16; ++kt) {
        const int k0 = kt * 64;
        __syncthreads();

#pragma unroll
        for (int i = 0; i < 8; ++i) {
            const int pl = i >> 1;
            const int row = r32 + (i & 1) * 32;
            *(uint4*)(kvs[pl] + row * QRS + ch * 8) =
                *(const uint4*)(kvg[pl] + (size_t)(k0 + row) * DMOD + ch * 8);
        }
        __syncthreads();

        float s[8][4];
#pragma unroll
        for (int ni = 0; ni < 8; ++ni)
#pragma unroll
            for (int r = 0; r < 4; ++r) s[ni][r] = 0.f;

#pragma unroll
        for (int ks = 0; ks < 4; ++ks) {
            uint32_t ah[4], al[4];
            ldmx4(ah[0], ah[1], ah[2], ah[3], sQh + a_off + ks * 32);
            ldmx4(al[0], al[1], al[2], al[3], sQl + a_off + ks * 32);
#pragma unroll
            for (int nb = 0; nb < 4; ++nb) {
                uint32_t kh[4], kl[4];
                ldmx4(kh[0], kh[1], kh[2], kh[3],
                      sKh + b_off + nb * 16 * (QRS * 2) + ks * 32);
                ldmx4(kl[0], kl[1], kl[2], kl[3],
                      sKl + b_off + nb * 16 * (QRS * 2) + ks * 32);
                uint32_t bh0[2] = {kh[0], kh[1]}, bh1[2] = {kh[2], kh[3]};
                uint32_t bl0[2] = {kl[0], kl[1]}, bl1[2] = {kl[2], kl[3]};
                mma16816(s[nb * 2],     ah, bh0);
                mma16816(s[nb * 2],     al, bh0);
                mma16816(s[nb * 2],     ah, bl0);
                mma16816(s[nb * 2 + 1], ah, bh1);
                mma16816(s[nb * 2 + 1], al, bh1);
                mma16816(s[nb * 2 + 1], ah, bl1);
            }
        }

        uint32_t ahf[4][4], alf[4][4];
        const int wq0 = q0 + w * 16;
        const int dmax = k0 + 63 - wq0;
        const int dmin = k0 - (wq0 + 15);

        if (dmax <= -10 || dmin >= 10) {
            const int cls = (dmax <= -10) ? 0 : 20;
            float* lacc = (dmax <= -10) ? l0a : l20a;
#pragma unroll
            for (int hf = 0; hf < 2; ++hf) {
                const int row = w * 16 + grp + hf * 8;
                const float ppc = pp[row * NR + cls];
                float acc = 0.f;
#pragma unroll
                for (int ni = 0; ni < 8; ++ni) {
                    const float f0 = (s[ni][hf * 2 + 0] + ppc) * S32;
                    const float f1 = (s[ni][hf * 2 + 1] + ppc) * S32;
                    acc += f0;
                    acc += f1;
                    __nv_bfloat16 h0, lo0, h1, lo1;
                    split2(f0, h0, lo0);
                    split2(f1, h1, lo1);
                    const int kc = ni >> 1;
                    const int sub = (ni & 1) * 2 + hf;
                    ahf[kc][sub] = pack_bf2(h0, h1);
                    alf[kc][sub] = pack_bf2(lo0, lo1);
                }
                lacc[hf] += acc;
            }
        } else {
#pragma unroll
            for (int ni = 0; ni < 8; ++ni) {
                const int colg = k0 + ni * 8 + tig * 2;
#pragma unroll
                for (int hf = 0; hf < 2; ++hf) {
                    const int row = w * 16 + grp + hf * 8;
                    const int gq = q0 + row;
                    const float* ppr = pp + row * NR;
                    const int d0 = colg - gq;
                    const int d1 = d0 + 1;
                    const int c0 = d0 < -10 ? 0 : (d0 > 10 ? 20 : d0 + 10);
                    const int c1 = d1 < -10 ? 0 : (d1 > 10 ? 20 : d1 + 10);
                    const float f0 = (s[ni][hf * 2 + 0] + ppr[c0]) * S32;
                    const float f1 = (s[ni][hf * 2 + 1] + ppr[c1]) * S32;
                    if (d0 <= -10)      l0a[hf]  += f0;
                    else if (d0 >= 10)  l20a[hf] += f0;
                    else                cs[row * NR + d0 + 10] += f0;
                    if (d1 <= -10)      l0a[hf]  += f1;
                    else if (d1 >= 10)  l20a[hf] += f1;
                    else                cs[row * NR + d1 + 10] += f1;
                    __nv_bfloat16 h0, lo0, h1, lo1;
                    split2(f0, h0, lo0);
                    split2(f1, h1, lo1);
                    const int kc = ni >> 1;
                    const int sub = (ni & 1) * 2 + hf;
                    ahf[kc][sub] = pack_bf2(h0, h1);
                    alf[kc][sub] = pack_bf2(lo0, lo1);
                }
            }
        }

#pragma unroll
        for (int kc = 0; kc < 4; ++kc) {
#pragma unroll
            for (int nb = 0; nb < 4; ++nb) {
                uint32_t vh[4], vl[4];
                ldmx4t(vh[0], vh[1], vh[2], vh[3],
                       sVh + (kc * 16 + vb_row) * (QRS * 2) + vb_cb + nb * 32);
                ldmx4t(vl[0], vl[1], vl[2], vl[3],
                       sVl + (kc * 16 + vb_row) * (QRS * 2) + vb_cb + nb * 32);
                uint32_t bh0[2] = {vh[0], vh[1]}, bh1[2] = {vh[2], vh[3]};
                uint32_t bl0[2] = {vl[0], vl[1]}, bl1[2] = {vl[2], vl[3]};
                mma16816(o[nb * 2],     ahf[kc], bh0);
                mma16816(o[nb * 2],     alf[kc], bh0);
                mma16816(o[nb * 2],     ahf[kc], bl0);
                mma16816(o[nb * 2 + 1], ahf[kc], bh1);
                mma16816(o[nb * 2 + 1], alf[kc], bh1);
                mma16816(o[nb * 2 + 1], ahf[kc], bl1);
            }
        }
    }

#pragma unroll
    for (int hf = 0; hf < 2; ++hf) {
        float v0 = l0a[hf];
        v0 += __shfl_xor_sync(0xffffffffu, v0, 1);
        v0 += __shfl_xor_sync(0xffffffffu, v0, 2);
        float v20 = l20a[hf];
        v20 += __shfl_xor_sync(0xffffffffu, v20, 1);
        v20 += __shfl_xor_sync(0xffffffffu, v20, 2);
        if (tig == 0) {
            const int row = w * 16 + grp + hf * 8;
            cs[row * NR + 0]  += v0;
            cs[row * NR + 20] += v20;
        }
    }
    __syncwarp();

#pragma unroll
    for (int ni = 0; ni < 8; ++ni) {
#pragma unroll
        for (int hf = 0; hf < 2; ++hf) {
            const int row = w * 16 + grp + hf * 8;
            const int col = ni * 8 + tig * 2;
            float a0 = o[ni][hf * 2 + 0];
            float a1 = o[ni][hf * 2 + 1];
            const float* csr = cs + row * NR;
#pragma unroll
            for (int j = 0; j < NR; ++j) {
                const float c = csr[j];
                a0 += c * rv[j * 64 + col];
                a1 += c * rv[j * 64 + col + 1];
            }
            __nv_bfloat16 h0, l0b, h1, l1b;
            split2(a0, h0, l0b);
            split2(a1, h1, l1b);
            const size_t base = ((size_t)b * SS + q0 + row) * K2 + hoff + col;
            *(__nv_bfloat162*)(x2 + base)        = __halves2bfloat162(h0, h1);
            *(__nv_bfloat162*)(x2 + base + 1024) = __halves2bfloat162(l0b, l1b);
        }
    }
}

// ============================================================================
// launch
// ============================================================================
extern "C" void kernel_launch(void* const* d_in, const int* in_sizes, int n_in,
                              void* d_out, int out_size) {
    const float* q   = (const float*)d_in[0];
    const float* k   = (const float*)d_in[1];
    const float* v   = (const float*)d_in[2];
    const float* Wq  = (const float*)d_in[4];
    const float* bq  = (const float*)d_in[5];
    const float* Wk  = (const float*)d_in[6];
    const float* bk  = (const float*)d_in[7];
    const float* Wv  = (const float*)d_in[8];
    const float* bv  = (const float*)d_in[9];
    const float* W0  = (const float*)d_in[10];
    const float* b0  = (const float*)d_in[11];
    const float* rkt = (const float*)d_in[12];
    const float* rvt = (const float*)d_in[13];

    __nv_bfloat16 *Qh, *Ql, *Kh, *Kl, *Vh, *Vl;
    cudaGetSymbolAddress((void**)&Qh, g_Qh);
    cudaGetSymbolAddress((void**)&Ql, g_Ql);
    cudaGetSymbolAddress((void**)&Kh, g_Kh);
    cudaGetSymbolAddress((void**)&Kl, g_Kl);
    cudaGetSymbolAddress((void**)&Vh, g_Vh);
    cudaGetSymbolAddress((void**)&Vl, g_Vl);
    __nv_bfloat16 *q2, *k2, *v2, *x2, *wq2, *wk2, *wv2, *w02;
    cudaGetSymbolAddress((void**)&q2, g_q2);
    cudaGetSymbolAddress((void**)&k2, g_k2);
    cudaGetSymbolAddress((void**)&v2, g_v2);
    cudaGetSymbolAddress((void**)&x2, g_x2);
    cudaGetSymbolAddress((void**)&wq2, g_wq2);
    cudaGetSymbolAddress((void**)&wk2, g_wk2);
    cudaGetSymbolAddress((void**)&wv2, g_wv2);
    cudaGetSymbolAddress((void**)&w02, g_w02);

    const int M = BB * SS;          // 2048
    const int NACT = M * DMOD;      // 2M
    const int NW = DMOD * DMOD;     // 1M

    // one batched split launch for all 7 tensors
    SplitPack sp;
    sp.in[0] = q;  sp.out[0] = q2;  sp.n[0] = NACT;
    sp.in[1] = k;  sp.out[1] = k2;  sp.n[1] = NACT;
    sp.in[2] = v;  sp.out[2] = v2;  sp.n[2] = NACT;
    sp.in[3] = Wq; sp.out[3] = wq2; sp.n[3] = NW;
    sp.in[4] = Wk; sp.out[4] = wk2; sp.n[4] = NW;
    sp.in[5] = Wv; sp.out[5] = wv2; sp.n[5] = NW;
    sp.in[6] = W0; sp.out[6] = w02; sp.n[6] = NW;
    split_multi<<<dim3(NACT / 256, 7), 256>>>(sp);

    cudaFuncSetAttribute(gemm_mma,
                         cudaFuncAttributeMaxDynamicSharedMemorySize, GSMEM);

    // fused q/k/v projections -> pre-split bf16 hi/lo planes
    GemmArgs pa;
    pa.A[0] = q2;  pa.A[1] = k2;  pa.A[2] = v2;
    pa.B[0] = wq2; pa.B[1] = wk2; pa.B[2] = wv2;
    pa.bias[0] = bq; pa.bias[1] = bk; pa.bias[2] = bv;
    pa.C[0] = pa.C[1] = pa.C[2] = nullptr;
    pa.Ch[0] = Qh; pa.Ch[1] = Kh; pa.Ch[2] = Vh;
    pa.Cl[0] = Ql; pa.Cl[1] = Kl; pa.Cl[2] = Vl;
    pa.mode = 1;
    gemm_mma<<<dim3(DMOD / 128, M / 128, 3), 256, GSMEM>>>(pa, DMOD);

    // tensor-core fused attention v5
    cudaFuncSetAttribute(attn_mma,
                         cudaFuncAttributeMaxDynamicSharedMemorySize, ATT_SMEM);
    attn_mma<<<dim3(SS / 128, HH, BB), 256, ATT_SMEM>>>(
        Qh, Ql, Kh, Kl, Vh, Vl, rkt, rvt, x2);

    // output projection (fp32 out)
    GemmArgs oa;
    oa.A[0] = x2;  oa.A[1] = x2;  oa.A[2] = x2;
    oa.B[0] = w02; oa.B[1] = w02; oa.B[2] = w02;
    oa.bias[0] = b0; oa.bias[1] = b0; oa.bias[2] = b0;
    oa.C[0] = (float*)d_out; oa.C[1] = (float*)d_out; oa.C[2] = (float*)d_out;
    oa.Ch[0] = oa.Ch[1] = oa.Ch[2] = nullptr;
    oa.Cl[0] = oa.Cl[1] = oa.Cl[2] = nullptr;
    oa.mode = 0;
    gemm_mma<<<dim3(DMOD / 128, M / 128, 1), 256, GSMEM>>>(oa, DMOD);
}